// round 14
// baseline (speedup 1.0000x reference)
#include <cuda_runtime.h>
#include <math.h>

#define BB 8
#define TT 2048
#define M_ROWS (BB*TT)   /* 16384 */
#define DVC 1024
#define DAC 128
#define IN_C 1152
#define D1C 512
#define D2C 128
#define DHP 272          /* 257 padded to mult of 16 */
#define DGC 128

typedef unsigned long long u64;

/* ---------------- scratch (static device globals; no allocs) ---------------- */
__device__ float g_y1[M_ROWS * D1C];
__device__ float g_xv2[M_ROWS * D2C];
__device__ float g_proj[M_ROWS * DHP];
__device__ float g_qproj[M_ROWS * DHP];
__device__ float g_gwT[256 * DHP];
__device__ float g_g12[M_ROWS * 256];
__device__ float g_x1p[2 * M_ROWS * DGC];   // fused col-split raw partials
__device__ float g_denp[2 * M_ROWS];        // fused col-split rowsum partials
__device__ float g_x2[M_ROWS * DGC];
__device__ float g_frame[M_ROWS];

/* ---------------- packed f32x2 helpers (Blackwell FFMA2) ---------------- */
__device__ __forceinline__ void ffma2(u64 &d, u64 a, u64 b) {
    asm("fma.rn.f32x2 %0, %1, %2, %0;" : "+l"(d) : "l"(a), "l"(b));
}
__device__ __forceinline__ u64 pack2(float x) {
    u64 r; asm("mov.b64 %0, {%1, %1};" : "=l"(r) : "f"(x)); return r;
}
__device__ __forceinline__ float2 unpk(u64 v) {
    float2 r; asm("mov.b64 {%0, %1}, %2;" : "=f"(r.x), "=f"(r.y) : "l"(v)); return r;
}

/* -------- generic 128x128 SGEMM, K-chunk 16, C = A[M,K] * B[N,K]^T -------- */
struct GemmP {
    const float* A; const float* Bm; float* C;
    int K, lda, ldb, ldc;
    const float* bias;
};

// MODE 0: C = leaky(acc + bias[n]) ; MODE 1: C = acc
template <int MODE>
__global__ __launch_bounds__(256, 2) void sgemm(GemmP p) {
    const int rowBase = blockIdx.y << 7;
    const int colBase = blockIdx.x << 7;

    __shared__ float As[2][16][128];
    __shared__ float Bs[2][16][128];
    const int tid = threadIdx.x;
    const int tx = tid & 15, ty = tid >> 4;
    const int lr = tid >> 1;
    const int lc = (tid & 1) << 3;          // 0 or 8
    const float* aPtr = p.A  + (long)(rowBase + lr) * p.lda + lc;
    const float* bPtr = p.Bm + (long)(colBase + lr) * p.ldb + lc;
    const int k_end = p.K >> 4;

    u64 acc[8][4];
#pragma unroll
    for (int i = 0; i < 8; i++)
#pragma unroll
        for (int j = 0; j < 4; j++) acc[i][j] = 0ULL;

    float4 av0 = *(const float4*)(aPtr);
    float4 av1 = *(const float4*)(aPtr + 4);
    float4 bv0 = *(const float4*)(bPtr);
    float4 bv1 = *(const float4*)(bPtr + 4);
    As[0][lc + 0][lr] = av0.x; As[0][lc + 1][lr] = av0.y;
    As[0][lc + 2][lr] = av0.z; As[0][lc + 3][lr] = av0.w;
    As[0][lc + 4][lr] = av1.x; As[0][lc + 5][lr] = av1.y;
    As[0][lc + 6][lr] = av1.z; As[0][lc + 7][lr] = av1.w;
    Bs[0][lc + 0][lr] = bv0.x; Bs[0][lc + 1][lr] = bv0.y;
    Bs[0][lc + 2][lr] = bv0.z; Bs[0][lc + 3][lr] = bv0.w;
    Bs[0][lc + 4][lr] = bv1.x; Bs[0][lc + 5][lr] = bv1.y;
    Bs[0][lc + 6][lr] = bv1.z; Bs[0][lc + 7][lr] = bv1.w;
    __syncthreads();

    for (int t = 0; t < k_end; t++) {
        const int cur = t & 1;
        if (t + 1 < k_end) {
            av0 = *(const float4*)(aPtr + ((t + 1) << 4));
            av1 = *(const float4*)(aPtr + ((t + 1) << 4) + 4);
            bv0 = *(const float4*)(bPtr + ((t + 1) << 4));
            bv1 = *(const float4*)(bPtr + ((t + 1) << 4) + 4);
        }
#pragma unroll
        for (int kk = 0; kk < 16; kk++) {
            float4 a0 = *(const float4*)&As[cur][kk][ty << 3];
            float4 a1 = *(const float4*)&As[cur][kk][(ty << 3) + 4];
            ulonglong2 q0 = *(const ulonglong2*)&Bs[cur][kk][tx << 3];
            ulonglong2 q1 = *(const ulonglong2*)&Bs[cur][kk][(tx << 3) + 4];
            const u64 bb0 = q0.x, bb1 = q0.y, bb2 = q1.x, bb3 = q1.y;
            float aa[8] = {a0.x, a0.y, a0.z, a0.w, a1.x, a1.y, a1.z, a1.w};
#pragma unroll
            for (int i = 0; i < 8; i++) {
                u64 a2 = pack2(aa[i]);
                ffma2(acc[i][0], a2, bb0);
                ffma2(acc[i][1], a2, bb1);
                ffma2(acc[i][2], a2, bb2);
                ffma2(acc[i][3], a2, bb3);
            }
        }
        if (t + 1 < k_end) {
            const int nxt = cur ^ 1;
            As[nxt][lc + 0][lr] = av0.x; As[nxt][lc + 1][lr] = av0.y;
            As[nxt][lc + 2][lr] = av0.z; As[nxt][lc + 3][lr] = av0.w;
            As[nxt][lc + 4][lr] = av1.x; As[nxt][lc + 5][lr] = av1.y;
            As[nxt][lc + 6][lr] = av1.z; As[nxt][lc + 7][lr] = av1.w;
            Bs[nxt][lc + 0][lr] = bv0.x; Bs[nxt][lc + 1][lr] = bv0.y;
            Bs[nxt][lc + 2][lr] = bv0.z; Bs[nxt][lc + 3][lr] = bv0.w;
            Bs[nxt][lc + 4][lr] = bv1.x; Bs[nxt][lc + 5][lr] = bv1.y;
            Bs[nxt][lc + 6][lr] = bv1.z; Bs[nxt][lc + 7][lr] = bv1.w;
            __syncthreads();
        }
    }

#pragma unroll
    for (int i = 0; i < 8; i++) {
        const int m = rowBase + (ty << 3) + i;
        float vals[8];
#pragma unroll
        for (int pq = 0; pq < 4; pq++) {
            float2 f = unpk(acc[i][pq]);
            vals[2 * pq] = f.x; vals[2 * pq + 1] = f.y;
        }
#pragma unroll
        for (int j8 = 0; j8 < 8; j8++) {
            float v = vals[j8];
            if (MODE == 0) {
                v += p.bias[colBase + (tx << 3) + j8];
                v = (v >= 0.f) ? v : 0.01f * v;
            }
            vals[j8] = v;
        }
        float4* dst = (float4*)&p.C[(long)m * p.ldc + colBase + (tx << 3)];
        dst[0] = make_float4(vals[0], vals[1], vals[2], vals[3]);
        dst[1] = make_float4(vals[4], vals[5], vals[6], vals[7]);
    }
}

/* -------- fused sim + softmax-denominator + adj matmul (flash-style) -------- */
struct FusedP {
    const float* qproj; const float* proj; const float* g12;
    float* x1p; float* denp; const int* seq;
};

#define ST_LD 132  /* St row stride: 16B-aligned, conflict-free */
#define FSM_BYTES ((4096 + 4096 + 4096 + 128 * ST_LD) * 4)

__global__ __launch_bounds__(512, 1) void fused_adj(FusedP p) {
    extern __shared__ float sm[];
    float* As = sm;                 // [2][16][128]
    float* Bs = sm + 4096;          // [2][16][128]
    float* Gs = sm + 8192;          // [2][16][128]
    float* St = sm + 12288;         // [128][ST_LD]

    const int b = blockIdx.z;
    const int rowBase = blockIdx.y << 7;
    const int split = blockIdx.x;
    const int L = p.seq[b];
    if (rowBase >= L) return;
    const int nct  = (L + 127) >> 7;
    const int half = (nct + 1) >> 1;
    const int j0 = split ? half : 0;
    const int j1 = split ? nct : half;
    if (j0 >= j1) return;

    const int tid = threadIdx.x;
    const int tx = tid & 15, tyy = tid >> 4;       // 16 x 32
    const int lr = tid >> 2, lc = (tid & 3) << 2;  // A/B staging
    const int grow = tid >> 5, gc4 = (tid & 31) << 2;  // G staging
    const long bTT = (long)b * TT;

    u64 xacc[4][4];
    float rs[4] = {0.f, 0.f, 0.f, 0.f};
#pragma unroll
    for (int i = 0; i < 4; i++)
#pragma unroll
        for (int j = 0; j < 4; j++) xacc[i][j] = 0ULL;

    const float* aPtr = p.qproj + (bTT + rowBase + lr) * DHP + lc;

    for (int jt = j0; jt < j1; jt++) {
        const int colBase = jt << 7;
        const float* bPtr = p.proj + (bTT + colBase + lr) * DHP + lc;

        /* ---- phase A: S = sim(qproj_rows, proj_cols), K = 272 ---- */
        u64 acc[4][4];
#pragma unroll
        for (int i = 0; i < 4; i++)
#pragma unroll
            for (int j = 0; j < 4; j++) acc[i][j] = 0ULL;

        float4 av = *(const float4*)(aPtr);
        float4 bv = *(const float4*)(bPtr);
        As[(lc + 0) * 128 + lr] = av.x; As[(lc + 1) * 128 + lr] = av.y;
        As[(lc + 2) * 128 + lr] = av.z; As[(lc + 3) * 128 + lr] = av.w;
        Bs[(lc + 0) * 128 + lr] = bv.x; Bs[(lc + 1) * 128 + lr] = bv.y;
        Bs[(lc + 2) * 128 + lr] = bv.z; Bs[(lc + 3) * 128 + lr] = bv.w;
        __syncthreads();

        for (int t = 0; t < 17; t++) {
            const int cur = (t & 1) * 2048;
            if (t < 16) {
                av = *(const float4*)(aPtr + ((t + 1) << 4));
                bv = *(const float4*)(bPtr + ((t + 1) << 4));
            }
#pragma unroll
            for (int kk = 0; kk < 16; kk++) {
                float4 a = *(const float4*)&As[cur + kk * 128 + (tyy << 2)];
                ulonglong2 q0 = *(const ulonglong2*)&Bs[cur + kk * 128 + (tx << 3)];
                ulonglong2 q1 = *(const ulonglong2*)&Bs[cur + kk * 128 + (tx << 3) + 4];
                u64 a0 = pack2(a.x), a1 = pack2(a.y), a2 = pack2(a.z), a3 = pack2(a.w);
                ffma2(acc[0][0], a0, q0.x); ffma2(acc[0][1], a0, q0.y);
                ffma2(acc[0][2], a0, q1.x); ffma2(acc[0][3], a0, q1.y);
                ffma2(acc[1][0], a1, q0.x); ffma2(acc[1][1], a1, q0.y);
                ffma2(acc[1][2], a1, q1.x); ffma2(acc[1][3], a1, q1.y);
                ffma2(acc[2][0], a2, q0.x); ffma2(acc[2][1], a2, q0.y);
                ffma2(acc[2][2], a2, q1.x); ffma2(acc[2][3], a2, q1.y);
                ffma2(acc[3][0], a3, q0.x); ffma2(acc[3][1], a3, q0.y);
                ffma2(acc[3][2], a3, q1.x); ffma2(acc[3][3], a3, q1.y);
            }
            if (t < 16) {
                const int nxt = ((t & 1) ^ 1) * 2048;
                As[nxt + (lc + 0) * 128 + lr] = av.x; As[nxt + (lc + 1) * 128 + lr] = av.y;
                As[nxt + (lc + 2) * 128 + lr] = av.z; As[nxt + (lc + 3) * 128 + lr] = av.w;
                Bs[nxt + (lc + 0) * 128 + lr] = bv.x; Bs[nxt + (lc + 1) * 128 + lr] = bv.y;
                Bs[nxt + (lc + 2) * 128 + lr] = bv.z; Bs[nxt + (lc + 3) * 128 + lr] = bv.w;
                __syncthreads();
            }
        }

        /* sim epilogue -> S values, row-sum partials, store to St */
#pragma unroll
        for (int i = 0; i < 4; i++) {
            float v[8];
#pragma unroll
            for (int pq = 0; pq < 4; pq++) {
                float2 f = unpk(acc[i][pq]);
                v[2 * pq] = f.x; v[2 * pq + 1] = f.y;
            }
            float rp = 0.f;
#pragma unroll
            for (int j8 = 0; j8 < 8; j8++) {
                const int n = colBase + (tx << 3) + j8;
                float e;
                if (n >= L) e = 0.f;
                else {
                    float xy = -v[j8];
                    if (xy > 1.03f) e = 1.0f;  // thr=0 -> exp(0)=1 (bit-exact)
                    else {
                        xy = fmaxf(xy, 1.0f);
                        float w  = xy + sqrtf(xy * xy - 1.0f + 1e-7f);
                        float x2v = 1.0f / w;
                        e = (x2v > 0.8f) ? expf(x2v) : 1.0f;
                    }
                }
                v[j8] = e;
                rp += e;
            }
            rs[i] += rp;
            float* sd = &St[(tyy * 4 + i) * ST_LD + (tx << 3)];
            *(float4*)(sd)     = make_float4(v[0], v[1], v[2], v[3]);
            *(float4*)(sd + 4) = make_float4(v[4], v[5], v[6], v[7]);
        }

        /* ---- phase B: xacc += S @ g1tile   (K = 128, g1 = g12 cols 0..127) ---- */
        const float* gBase = p.g12 + (bTT + colBase) * 256;
        float4 gv = *(const float4*)(gBase + (long)grow * 256 + gc4);
        Gs[grow * 128 + gc4 + 0] = gv.x; Gs[grow * 128 + gc4 + 1] = gv.y;
        Gs[grow * 128 + gc4 + 2] = gv.z; Gs[grow * 128 + gc4 + 3] = gv.w;
        __syncthreads();

        for (int t = 0; t < 8; t++) {
            const int cur = (t & 1) * 2048;
            if (t < 7)
                gv = *(const float4*)(gBase + (long)((t + 1) * 16 + grow) * 256 + gc4);
#pragma unroll
            for (int kk = 0; kk < 16; kk++) {
                const int kq = t * 16 + kk;
                u64 a0 = pack2(St[(tyy * 4 + 0) * ST_LD + kq]);
                u64 a1 = pack2(St[(tyy * 4 + 1) * ST_LD + kq]);
                u64 a2 = pack2(St[(tyy * 4 + 2) * ST_LD + kq]);
                u64 a3 = pack2(St[(tyy * 4 + 3) * ST_LD + kq]);
                ulonglong2 q0 = *(const ulonglong2*)&Gs[cur + kk * 128 + (tx << 3)];
                ulonglong2 q1 = *(const ulonglong2*)&Gs[cur + kk * 128 + (tx << 3) + 4];
                ffma2(xacc[0][0], a0, q0.x); ffma2(xacc[0][1], a0, q0.y);
                ffma2(xacc[0][2], a0, q1.x); ffma2(xacc[0][3], a0, q1.y);
                ffma2(xacc[1][0], a1, q0.x); ffma2(xacc[1][1], a1, q0.y);
                ffma2(xacc[1][2], a1, q1.x); ffma2(xacc[1][3], a1, q1.y);
                ffma2(xacc[2][0], a2, q0.x); ffma2(xacc[2][1], a2, q0.y);
                ffma2(xacc[2][2], a2, q1.x); ffma2(xacc[2][3], a2, q1.y);
                ffma2(xacc[3][0], a3, q0.x); ffma2(xacc[3][1], a3, q0.y);
                ffma2(xacc[3][2], a3, q1.x); ffma2(xacc[3][3], a3, q1.y);
            }
            if (t < 7) {
                const int nxt = ((t & 1) ^ 1) * 2048;
                Gs[nxt + grow * 128 + gc4 + 0] = gv.x;
                Gs[nxt + grow * 128 + gc4 + 1] = gv.y;
                Gs[nxt + grow * 128 + gc4 + 2] = gv.z;
                Gs[nxt + grow * 128 + gc4 + 3] = gv.w;
                __syncthreads();
            }
        }
        __syncthreads();   // protect St/Gs before next tile's reuse
    }

    /* ---- write raw x1 partials + rowsum partials ---- */
#pragma unroll
    for (int i = 0; i < 4; i++) {
        const int m = rowBase + tyy * 4 + i;
        float rp = rs[i];
        rp += __shfl_down_sync(0xffffffffu, rp, 8, 16);
        rp += __shfl_down_sync(0xffffffffu, rp, 4, 16);
        rp += __shfl_down_sync(0xffffffffu, rp, 2, 16);
        rp += __shfl_down_sync(0xffffffffu, rp, 1, 16);
        if (tx == 0) p.denp[(size_t)split * M_ROWS + bTT + m] = rp;
        float w[8];
#pragma unroll
        for (int pq = 0; pq < 4; pq++) {
            float2 f = unpk(xacc[i][pq]);
            w[2 * pq] = f.x; w[2 * pq + 1] = f.y;
        }
        float* dst = &p.x1p[((size_t)split * M_ROWS + bTT + m) * DGC + (tx << 3)];
        *(float4*)(dst)     = make_float4(w[0], w[1], w[2], w[3]);
        *(float4*)(dst + 4) = make_float4(w[4], w[5], w[6], w[7]);
    }
}

/* ---------------- small kernels ---------------- */
__global__ void prep_gwT(const float* gw1, const float* gw2, float* gwT) {
    int idx = blockIdx.x * 256 + threadIdx.x;
    if (idx >= 256 * DHP) return;
    int r = idx / DHP, k = idx % DHP;
    float v = 0.f;
    if (k < 257) v = (r < 128) ? gw1[k * 128 + r] : gw2[k * 128 + (r - 128)];
    gwT[idx] = v;
}

__global__ void proj_kernel(const float* xv2, const float* inputs,
                            float* proj, float* qproj) {
    const int row = blockIdx.x;
    const int tid = threadIdx.x;  // 256
    float x = (tid < 128) ? xv2[row * 128 + tid]
                          : inputs[(long)row * IN_C + DVC + (tid - 128)];
    float ss = x * x;
    for (int o = 16; o > 0; o >>= 1) ss += __shfl_down_sync(0xffffffffu, ss, o);
    __shared__ float red[8];
    if ((tid & 31) == 0) red[tid >> 5] = ss;
    __syncthreads();
    __shared__ float nrm;
    if (tid == 0) {
        float t = ((red[0] + red[1]) + (red[2] + red[3])) +
                  ((red[4] + red[5]) + (red[6] + red[7]));
        nrm = sqrtf(fmaxf(t, 1e-12f));
    }
    __syncthreads();
    float nn = nrm;
    float sh = sinhf(nn) / nn;
    float* pr = proj  + (long)row * DHP;
    float* qr = qproj + (long)row * DHP;
    float val = sh * x;
    pr[1 + tid] = val;
    qr[1 + tid] = val;
    if (tid == 0) { float ch = coshf(nn); pr[0] = ch; qr[0] = -ch; }
    if (tid < 15) { pr[257 + tid] = 0.f; qr[257 + tid] = 0.f; }
}

// disadj @ y via windowed forward+backward exponential scan (r^128 ~ 4e-21)
#define SC 64
#define SHALO 128
__global__ void scan_kernel(const float* g12, float* x2) {
    const int b = blockIdx.x;
    const int c = blockIdx.y;
    const int ch = threadIdx.x;        // 128 channels
    const float r = 0.69220062755534635f;  // exp(-exp(-1))
    __shared__ float sf[SC][DGC];
    const int s = c * SC;
    int i0 = s - SHALO; if (i0 < 0) i0 = 0;
    float f = 0.f;
    for (int i = i0; i < s + SC; i++) {
        float y = g12[((long)(b * TT + i)) * 256 + 128 + ch];
        f = fmaf(r, f, y);
        if (i >= s) sf[i - s][ch] = f;
    }
    int i1 = s + SC + SHALO; if (i1 > TT) i1 = TT;
    float bk = 0.f;
    for (int i = i1 - 1; i >= s; i--) {
        float y = g12[((long)(b * TT + i)) * 256 + 128 + ch];
        bk = fmaf(r, bk, y);
        if (i < s + SC) {
            float v = sf[i - s][ch] + bk - y;
            v = (v >= 0.f) ? v : 0.01f * v;
            x2[((long)(b * TT + i)) * DGC + ch] = v;
        }
    }
}

__global__ void frame_kernel(const float* x1p, const float* x2,
                             const float* denp, const int* seq,
                             const float* cls_w, const float* cls_b,
                             float* frame, float* out) {
    int warp = threadIdx.x >> 5, lane = threadIdx.x & 31;
    int row = blockIdx.x * 8 + warp;
    const int b = row >> 11;           // row / TT
    const int m = row & (TT - 1);
    const int L = seq[b];
    float s = 0.f;
    if (m < L) {
        float inv = 1.0f / (denp[row] + denp[M_ROWS + row]);
        const float* p0 = x1p + (size_t)row * DGC;
        const float* p1 = p0 + (size_t)M_ROWS * DGC;
        for (int d = lane; d < DGC; d += 32) {
            float v = (p0[d] + p1[d]) * inv;
            v = (v >= 0.f) ? v : 0.01f * v;
            float sg = (d == 0) ? -1.0f : 1.0f;
            s += sg * v * cls_w[d];
        }
    }
    const float* xr2 = x2 + (size_t)row * DGC;
    for (int d = lane; d < DGC; d += 32)
        s += xr2[d] * cls_w[DGC + d];
    for (int o = 16; o > 0; o >>= 1) s += __shfl_down_sync(0xffffffffu, s, o);
    if (lane == 0) {
        float v = 2.0f + 2.0f * s + cls_b[0];
        frame[row] = v;
        out[8 + row] = v;
    }
}

__global__ void clas_kernel(const float* frame, const int* seq_len, float* out) {
    __shared__ float s[TT];
    __shared__ float red[1024];
    const int b = blockIdx.x, tid = threadIdx.x;
    const int L = seq_len[b];
    for (int t = tid; t < TT; t += 1024)
        s[t] = (t < L) ? frame[b * TT + t] : -1e30f;
    __syncthreads();
    for (int size = 2; size <= TT; size <<= 1) {
        for (int stride = size >> 1; stride > 0; stride >>= 1) {
            for (int i = tid; i < TT; i += 1024) {
                int l = i ^ stride;
                if (l > i) {
                    float a = s[i], c = s[l];
                    bool desc = ((i & size) == 0);
                    if (desc ? (a < c) : (a > c)) { s[i] = c; s[l] = a; }
                }
            }
            __syncthreads();
        }
    }
    int k = L / 16 + 1;
    float ps = 0.f;
    for (int t = tid; t < k; t += 1024) ps += s[t];
    red[tid] = ps;
    __syncthreads();
    for (int st = 512; st > 0; st >>= 1) {
        if (tid < st) red[tid] += red[tid + st];
        __syncthreads();
    }
    if (tid == 0) {
        float m = red[0] / (float)k;
        out[b] = 1.0f / (1.0f + expf(-m));
    }
}

/* ---------------- host orchestration ---------------- */
extern "C" void kernel_launch(void* const* d_in, const int* in_sizes, int n_in,
                              void* d_out, int out_size) {
    const float* inputs = (const float*)d_in[0];
    const int*   seq    = (const int*)d_in[1];
    const float* w1     = (const float*)d_in[2];
    const float* b1     = (const float*)d_in[3];
    const float* w2     = (const float*)d_in[4];
    const float* b2     = (const float*)d_in[5];
    const float* gw1    = (const float*)d_in[6];
    const float* gw2    = (const float*)d_in[7];
    const float* cls_w  = (const float*)d_in[8];
    const float* cls_b  = (const float*)d_in[9];
    float* out = (float*)d_out;

    float *y1, *xv2, *proj, *qproj, *gwT, *g12, *x1p, *denp, *x2, *frame;
    cudaGetSymbolAddress((void**)&y1,    g_y1);
    cudaGetSymbolAddress((void**)&xv2,   g_xv2);
    cudaGetSymbolAddress((void**)&proj,  g_proj);
    cudaGetSymbolAddress((void**)&qproj, g_qproj);
    cudaGetSymbolAddress((void**)&gwT,   g_gwT);
    cudaGetSymbolAddress((void**)&g12,   g_g12);
    cudaGetSymbolAddress((void**)&x1p,   g_x1p);
    cudaGetSymbolAddress((void**)&denp,  g_denp);
    cudaGetSymbolAddress((void**)&x2,    g_x2);
    cudaGetSymbolAddress((void**)&frame, g_frame);

    cudaFuncSetAttribute(fused_adj, cudaFuncAttributeMaxDynamicSharedMemorySize,
                         FSM_BYTES);

    prep_gwT<<<(256 * DHP + 255) / 256, 256>>>(gw1, gw2, gwT);

    // GEMM1: y1 = leaky(inputs[:, :1024] @ w1^T + b1)   M=16384 N=512 K=1024
    {
        GemmP p = { inputs, w1, y1, DVC, IN_C, DVC, D1C, b1 };
        sgemm<0><<<dim3(D1C / 128, M_ROWS / 128, 1), 256>>>(p);
    }
    // GEMM2: xv2 = leaky(y1 @ w2^T + b2)   M=16384 N=128 K=512
    {
        GemmP p = { y1, w2, xv2, D1C, D1C, D1C, D2C, b2 };
        sgemm<0><<<dim3(1, M_ROWS / 128, 1), 256>>>(p);
    }
    proj_kernel<<<M_ROWS, 256>>>(xv2, inputs, proj, qproj);

    // g12 = proj @ [gw1 | gw2]   M=16384 N=256 K=272
    {
        GemmP p = { proj, gwT, g12, DHP, DHP, DHP, 256, nullptr };
        sgemm<1><<<dim3(2, M_ROWS / 128, 1), 256>>>(p);
    }

    // fused: sim tile -> E tile (smem) -> rowsums + E @ g1, col-split(2)
    {
        FusedP p = { qproj, proj, g12, x1p, denp, seq };
        fused_adj<<<dim3(2, TT / 128, BB), 512, FSM_BYTES>>>(p);
    }
    // x2 = leaky(disadj @ g2) via windowed exponential scan
    scan_kernel<<<dim3(BB, TT / SC), DGC>>>(g12, x2);

    // frame_prob: combine col-split partials, /denom, leaky, classifier dot
    frame_kernel<<<M_ROWS / 8, 256>>>(x1p, x2, denp, seq, cls_w, cls_b, frame, out);
    clas_kernel<<<BB, 1024>>>(frame, seq, out);
}

// round 15
// speedup vs baseline: 1.2744x; 1.2744x over previous
#include <cuda_runtime.h>
#include <math.h>

#define BB 8
#define TT 2048
#define M_ROWS (BB*TT)   /* 16384 */
#define DVC 1024
#define DAC 128
#define IN_C 1152
#define D1C 512
#define D2C 128
#define DHP 272          /* 257 padded to mult of 16 */
#define DGC 128

typedef unsigned long long u64;

/* ---------------- scratch (static device globals; no allocs) ---------------- */
__device__ float g_y1[M_ROWS * D1C];
__device__ float g_xv2[M_ROWS * D2C];
__device__ float g_proj[M_ROWS * DHP];
__device__ float g_qproj[M_ROWS * DHP];
__device__ float g_gwT[256 * DHP];
__device__ float g_g12[M_ROWS * 256];
__device__ float g_g1T[BB * DGC * TT];
__device__ float g_E[(size_t)BB * TT * TT]; // 134 MB
__device__ float g_denom[M_ROWS];
__device__ float g_x1p[2 * M_ROWS * DGC];   // adj split-K raw partials
__device__ float g_x2[M_ROWS * DGC];
__device__ float g_frame[M_ROWS];

/* ---------------- packed f32x2 helpers (Blackwell FFMA2) ---------------- */
__device__ __forceinline__ void ffma2(u64 &d, u64 a, u64 b) {
    asm("fma.rn.f32x2 %0, %1, %2, %0;" : "+l"(d) : "l"(a), "l"(b));
}
__device__ __forceinline__ u64 pack2(float x) {
    u64 r; asm("mov.b64 %0, {%1, %1};" : "=l"(r) : "f"(x)); return r;
}
__device__ __forceinline__ float2 unpk(u64 v) {
    float2 r; asm("mov.b64 {%0, %1}, %2;" : "=f"(r.x), "=f"(r.y) : "l"(v)); return r;
}

/* ---- generic MTx128 SGEMM (MT=128 or 64), K-chunk 16, C = A * B^T ---- */
struct GemmP {
    const float* A; const float* Bm; float* C;
    int K, lda, ldb, ldc;
    long aS, bS, cS;            // per-blockIdx.z strides
    long splitStride;           // MODE3: offset between K-split partial buffers
    const float* bias;
    const int* seq;
    float* denom;               // MODE2: atomic row-sum output
};

// MODE 0: C = leaky(acc + bias[n])
// MODE 1: C = acc
// MODE 2: similarity -> E (tile-skipped by seq_len) + fused row-sum atomics
// MODE 3: raw adj matmul partials, split-K over gridDim.x, K clamped to ceil16(L)
template <int MODE, int MT>
__global__ __launch_bounds__(256, 2) void sgemm(GemmP p) {
    const int z = blockIdx.z;
    const int rowBase = blockIdx.y * MT;
    int colBase, split;
    if (MODE == 3) { colBase = 0; split = blockIdx.x; }
    else           { colBase = blockIdx.x << 7; split = 0; }

    int L = 0;
    if (MODE >= 2) L = p.seq[z];
    if (MODE == 2 && (rowBase >= L || colBase >= L)) return;   // tile never read
    if (MODE == 3 && rowBase >= L) return;                     // output rows masked

    int k_begin = 0, k_end = p.K >> 4;      // chunks of 16
    if (MODE == 3) {
        const int nk_eff = (L + 15) >> 4;   // E cols >= ceil16(L) are zero
        const int half   = (nk_eff + 1) >> 1;
        k_begin = split ? half : 0;
        k_end   = split ? nk_eff : half;
    }

    constexpr int RPT = MT / 16;            // rows per thread: 8 or 4
    __shared__ float As[2][16][MT];
    __shared__ float Bs[2][16][128];
    const float* A  = p.A  + (long)z * p.aS;
    const float* Bm = p.Bm + (long)z * p.bS;
    float*       C  = p.C  + (long)z * p.cS + (long)split * p.splitStride;
    const int tid = threadIdx.x;
    const int tx = tid & 15, ty = tid >> 4;
    const int lrB = tid >> 1;
    const int lcB = (tid & 1) << 3;         // 0 or 8
    const int lrA = (MT == 128) ? (tid >> 1) : (tid >> 2);
    const int lcA = (MT == 128) ? ((tid & 1) << 3) : ((tid & 3) << 2);
    const float* aPtr = A  + (long)(rowBase + lrA) * p.lda + lcA;
    const float* bPtr = Bm + (long)(colBase + lrB) * p.ldb + lcB;

    u64 acc[RPT][4];
#pragma unroll
    for (int i = 0; i < RPT; i++)
#pragma unroll
        for (int j = 0; j < 4; j++) acc[i][j] = 0ULL;

    // prologue: stage first chunk
    {
        float4 a0 = *(const float4*)(aPtr + (k_begin << 4));
        As[0][lcA + 0][lrA] = a0.x; As[0][lcA + 1][lrA] = a0.y;
        As[0][lcA + 2][lrA] = a0.z; As[0][lcA + 3][lrA] = a0.w;
        if (MT == 128) {
            float4 a1 = *(const float4*)(aPtr + (k_begin << 4) + 4);
            As[0][lcA + 4][lrA] = a1.x; As[0][lcA + 5][lrA] = a1.y;
            As[0][lcA + 6][lrA] = a1.z; As[0][lcA + 7][lrA] = a1.w;
        }
        float4 b0 = *(const float4*)(bPtr + (k_begin << 4));
        float4 b1 = *(const float4*)(bPtr + (k_begin << 4) + 4);
        Bs[0][lcB + 0][lrB] = b0.x; Bs[0][lcB + 1][lrB] = b0.y;
        Bs[0][lcB + 2][lrB] = b0.z; Bs[0][lcB + 3][lrB] = b0.w;
        Bs[0][lcB + 4][lrB] = b1.x; Bs[0][lcB + 5][lrB] = b1.y;
        Bs[0][lcB + 6][lrB] = b1.z; Bs[0][lcB + 7][lrB] = b1.w;
    }
    __syncthreads();

    float4 av0, av1, bv0, bv1;
    for (int t = k_begin; t < k_end; t++) {
        const int cur = (t - k_begin) & 1;
        if (t + 1 < k_end) {
            av0 = *(const float4*)(aPtr + ((t + 1) << 4));
            if (MT == 128) av1 = *(const float4*)(aPtr + ((t + 1) << 4) + 4);
            bv0 = *(const float4*)(bPtr + ((t + 1) << 4));
            bv1 = *(const float4*)(bPtr + ((t + 1) << 4) + 4);
        }
#pragma unroll
        for (int kk = 0; kk < 16; kk++) {
            float aa[RPT];
            if (MT == 128) {
                float4 a0 = *(const float4*)&As[cur][kk][ty << 3];
                float4 a1 = *(const float4*)&As[cur][kk][(ty << 3) + 4];
                aa[0] = a0.x; aa[1] = a0.y; aa[2] = a0.z; aa[3] = a0.w;
                aa[4] = a1.x; aa[5] = a1.y; aa[6] = a1.z; aa[7] = a1.w;
            } else {
                float4 a0 = *(const float4*)&As[cur][kk][ty << 2];
                aa[0] = a0.x; aa[1] = a0.y; aa[2] = a0.z; aa[3] = a0.w;
            }
            ulonglong2 q0 = *(const ulonglong2*)&Bs[cur][kk][tx << 3];
            ulonglong2 q1 = *(const ulonglong2*)&Bs[cur][kk][(tx << 3) + 4];
            const u64 bb0 = q0.x, bb1 = q0.y, bb2 = q1.x, bb3 = q1.y;
#pragma unroll
            for (int i = 0; i < RPT; i++) {
                u64 a2 = pack2(aa[i]);
                ffma2(acc[i][0], a2, bb0);
                ffma2(acc[i][1], a2, bb1);
                ffma2(acc[i][2], a2, bb2);
                ffma2(acc[i][3], a2, bb3);
            }
        }
        if (t + 1 < k_end) {
            const int nxt = cur ^ 1;
            As[nxt][lcA + 0][lrA] = av0.x; As[nxt][lcA + 1][lrA] = av0.y;
            As[nxt][lcA + 2][lrA] = av0.z; As[nxt][lcA + 3][lrA] = av0.w;
            if (MT == 128) {
                As[nxt][lcA + 4][lrA] = av1.x; As[nxt][lcA + 5][lrA] = av1.y;
                As[nxt][lcA + 6][lrA] = av1.z; As[nxt][lcA + 7][lrA] = av1.w;
            }
            Bs[nxt][lcB + 0][lrB] = bv0.x; Bs[nxt][lcB + 1][lrB] = bv0.y;
            Bs[nxt][lcB + 2][lrB] = bv0.z; Bs[nxt][lcB + 3][lrB] = bv0.w;
            Bs[nxt][lcB + 4][lrB] = bv1.x; Bs[nxt][lcB + 5][lrB] = bv1.y;
            Bs[nxt][lcB + 6][lrB] = bv1.z; Bs[nxt][lcB + 7][lrB] = bv1.w;
            __syncthreads();
        }
    }

#pragma unroll
    for (int i = 0; i < RPT; i++) {
        const int m = rowBase + ty * RPT + i;
        float vals[8];
#pragma unroll
        for (int pq = 0; pq < 4; pq++) {
            float2 f = unpk(acc[i][pq]);
            vals[2 * pq] = f.x; vals[2 * pq + 1] = f.y;
        }
#pragma unroll
        for (int j8 = 0; j8 < 8; j8++) {
            const int n = colBase + (tx << 3) + j8;
            float v = vals[j8];
            if (MODE == 0) {
                v += p.bias[n];
                v = (v >= 0.f) ? v : 0.01f * v;
            } else if (MODE == 2) {
                if (n >= L) v = 0.f;
                else {
                    float xy = -v;
                    if (xy > 1.03f) {
                        v = 1.0f;   // x2 < 0.8 guaranteed -> thr=0 -> exp(0)=1
                    } else {
                        xy = fmaxf(xy, 1.0f);
                        float w  = xy + sqrtf(xy * xy - 1.0f + 1e-7f);
                        float x2v = 1.0f / w;
                        v = (x2v > 0.8f) ? expf(x2v) : 1.0f;
                    }
                }
            }
            // MODE 1 / 3: raw accumulator out
            vals[j8] = v;
        }
        if (MODE == 2) {
            float rp = ((vals[0] + vals[1]) + (vals[2] + vals[3])) +
                       ((vals[4] + vals[5]) + (vals[6] + vals[7]));
            rp += __shfl_down_sync(0xffffffffu, rp, 8, 16);
            rp += __shfl_down_sync(0xffffffffu, rp, 4, 16);
            rp += __shfl_down_sync(0xffffffffu, rp, 2, 16);
            rp += __shfl_down_sync(0xffffffffu, rp, 1, 16);
            if (tx == 0) atomicAdd(&p.denom[z * TT + m], rp);
        }
        float4* dst = (float4*)&C[(long)m * p.ldc + colBase + (tx << 3)];
        dst[0] = make_float4(vals[0], vals[1], vals[2], vals[3]);
        dst[1] = make_float4(vals[4], vals[5], vals[6], vals[7]);
    }
}

/* ---------------- small kernels ---------------- */
__global__ void zero_denom(float* denom) {
    denom[blockIdx.x * 1024 + threadIdx.x] = 0.f;
}

__global__ void prep_gwT(const float* gw1, const float* gw2, float* gwT) {
    int idx = blockIdx.x * 256 + threadIdx.x;
    if (idx >= 256 * DHP) return;
    int r = idx / DHP, k = idx % DHP;
    float v = 0.f;
    if (k < 257) v = (r < 128) ? gw1[k * 128 + r] : gw2[k * 128 + (r - 128)];
    gwT[idx] = v;
}

__global__ void proj_kernel(const float* xv2, const float* inputs,
                            float* proj, float* qproj) {
    const int row = blockIdx.x;
    const int tid = threadIdx.x;  // 256
    float x = (tid < 128) ? xv2[row * 128 + tid]
                          : inputs[(long)row * IN_C + DVC + (tid - 128)];
    float ss = x * x;
    for (int o = 16; o > 0; o >>= 1) ss += __shfl_down_sync(0xffffffffu, ss, o);
    __shared__ float red[8];
    if ((tid & 31) == 0) red[tid >> 5] = ss;
    __syncthreads();
    __shared__ float nrm;
    if (tid == 0) {
        float t = ((red[0] + red[1]) + (red[2] + red[3])) +
                  ((red[4] + red[5]) + (red[6] + red[7]));
        nrm = sqrtf(fmaxf(t, 1e-12f));
    }
    __syncthreads();
    float nn = nrm;
    float sh = sinhf(nn) / nn;
    float* pr = proj  + (long)row * DHP;
    float* qr = qproj + (long)row * DHP;
    float val = sh * x;
    pr[1 + tid] = val;
    qr[1 + tid] = val;
    if (tid == 0) { float ch = coshf(nn); pr[0] = ch; qr[0] = -ch; }
    if (tid < 15) { pr[257 + tid] = 0.f; qr[257 + tid] = 0.f; }
}

__global__ void transpose_g1(const float* g12, float* g1T) {
    __shared__ float tile[32][33];
    int b = blockIdx.z;
    int t0 = blockIdx.x * 32, n0 = blockIdx.y * 32;
    for (int r = threadIdx.y; r < 32; r += 8)
        tile[r][threadIdx.x] = g12[((long)(b * TT + t0 + r)) * 256 + n0 + threadIdx.x];
    __syncthreads();
    for (int r = threadIdx.y; r < 32; r += 8)
        g1T[(long)b * DGC * TT + (long)(n0 + r) * TT + t0 + threadIdx.x] = tile[threadIdx.x][r];
}

// disadj @ y via windowed forward+backward exponential scan (r^128 ~ 4e-21)
#define SC 64
#define SHALO 128
__global__ void scan_kernel(const float* g12, float* x2) {
    const int b = blockIdx.x;
    const int c = blockIdx.y;
    const int ch = threadIdx.x;        // 128 channels
    const float r = 0.69220062755534635f;  // exp(-exp(-1))
    __shared__ float sf[SC][DGC];
    const int s = c * SC;
    int i0 = s - SHALO; if (i0 < 0) i0 = 0;
    float f = 0.f;
    for (int i = i0; i < s + SC; i++) {
        float y = g12[((long)(b * TT + i)) * 256 + 128 + ch];
        f = fmaf(r, f, y);
        if (i >= s) sf[i - s][ch] = f;
    }
    int i1 = s + SC + SHALO; if (i1 > TT) i1 = TT;
    float bk = 0.f;
    for (int i = i1 - 1; i >= s; i--) {
        float y = g12[((long)(b * TT + i)) * 256 + 128 + ch];
        bk = fmaf(r, bk, y);
        if (i < s + SC) {
            float v = sf[i - s][ch] + bk - y;
            v = (v >= 0.f) ? v : 0.01f * v;
            x2[((long)(b * TT + i)) * DGC + ch] = v;
        }
    }
}

__global__ void frame_kernel(const float* x1p, const float* x2,
                             const float* denom, const int* seq,
                             const float* cls_w, const float* cls_b,
                             float* frame, float* out) {
    int warp = threadIdx.x >> 5, lane = threadIdx.x & 31;
    int row = blockIdx.x * 8 + warp;
    const int b = row >> 11;           // row / TT
    const int m = row & (TT - 1);
    const int L = seq[b];
    float s = 0.f;
    if (m < L) {
        float inv = 1.0f / denom[row];
        const float* p0 = x1p + (size_t)row * DGC;
        const float* p1 = p0 + (size_t)M_ROWS * DGC;
        for (int d = lane; d < DGC; d += 32) {
            float v = (p0[d] + p1[d]) * inv;
            v = (v >= 0.f) ? v : 0.01f * v;
            float sg = (d == 0) ? -1.0f : 1.0f;
            s += sg * v * cls_w[d];
        }
    }
    const float* xr2 = x2 + (size_t)row * DGC;
    for (int d = lane; d < DGC; d += 32)
        s += xr2[d] * cls_w[DGC + d];
    for (int o = 16; o > 0; o >>= 1) s += __shfl_down_sync(0xffffffffu, s, o);
    if (lane == 0) {
        float v = 2.0f + 2.0f * s + cls_b[0];
        frame[row] = v;
        out[8 + row] = v;
    }
}

__global__ void clas_kernel(const float* frame, const int* seq_len, float* out) {
    __shared__ float s[TT];
    __shared__ float red[1024];
    const int b = blockIdx.x, tid = threadIdx.x;
    const int L = seq_len[b];
    for (int t = tid; t < TT; t += 1024)
        s[t] = (t < L) ? frame[b * TT + t] : -1e30f;
    __syncthreads();
    for (int size = 2; size <= TT; size <<= 1) {
        for (int stride = size >> 1; stride > 0; stride >>= 1) {
            for (int i = tid; i < TT; i += 1024) {
                int l = i ^ stride;
                if (l > i) {
                    float a = s[i], c = s[l];
                    bool desc = ((i & size) == 0);
                    if (desc ? (a < c) : (a > c)) { s[i] = c; s[l] = a; }
                }
            }
            __syncthreads();
        }
    }
    int k = L / 16 + 1;
    float ps = 0.f;
    for (int t = tid; t < k; t += 1024) ps += s[t];
    red[tid] = ps;
    __syncthreads();
    for (int st = 512; st > 0; st >>= 1) {
        if (tid < st) red[tid] += red[tid + st];
        __syncthreads();
    }
    if (tid == 0) {
        float m = red[0] / (float)k;
        out[b] = 1.0f / (1.0f + expf(-m));
    }
}

/* ---------------- host orchestration ---------------- */
extern "C" void kernel_launch(void* const* d_in, const int* in_sizes, int n_in,
                              void* d_out, int out_size) {
    const float* inputs = (const float*)d_in[0];
    const int*   seq    = (const int*)d_in[1];
    const float* w1     = (const float*)d_in[2];
    const float* b1     = (const float*)d_in[3];
    const float* w2     = (const float*)d_in[4];
    const float* b2     = (const float*)d_in[5];
    const float* gw1    = (const float*)d_in[6];
    const float* gw2    = (const float*)d_in[7];
    const float* cls_w  = (const float*)d_in[8];
    const float* cls_b  = (const float*)d_in[9];
    float* out = (float*)d_out;

    float *y1, *xv2, *proj, *qproj, *gwT, *g12, *g1T, *E, *denom, *x1p, *x2, *frame;
    cudaGetSymbolAddress((void**)&y1,    g_y1);
    cudaGetSymbolAddress((void**)&xv2,   g_xv2);
    cudaGetSymbolAddress((void**)&proj,  g_proj);
    cudaGetSymbolAddress((void**)&qproj, g_qproj);
    cudaGetSymbolAddress((void**)&gwT,   g_gwT);
    cudaGetSymbolAddress((void**)&g12,   g_g12);
    cudaGetSymbolAddress((void**)&g1T,   g_g1T);
    cudaGetSymbolAddress((void**)&E,     g_E);
    cudaGetSymbolAddress((void**)&denom, g_denom);
    cudaGetSymbolAddress((void**)&x1p,   g_x1p);
    cudaGetSymbolAddress((void**)&x2,    g_x2);
    cudaGetSymbolAddress((void**)&frame, g_frame);

    zero_denom<<<M_ROWS / 1024, 1024>>>(denom);
    prep_gwT<<<(256 * DHP + 255) / 256, 256>>>(gw1, gw2, gwT);

    // GEMM1: y1 = leaky(inputs[:, :1024] @ w1^T + b1)   M=16384 N=512 K=1024
    {
        GemmP p = { inputs, w1, y1, DVC, IN_C, DVC, D1C, 0, 0, 0, 0, b1, nullptr, nullptr };
        sgemm<0, 128><<<dim3(D1C / 128, M_ROWS / 128, 1), 256>>>(p);
    }
    // GEMM2: xv2 = leaky(y1 @ w2^T + b2)   M=16384 N=128 K=512  (M64 tiles -> 256 CTAs)
    {
        GemmP p = { y1, w2, xv2, D1C, D1C, D1C, D2C, 0, 0, 0, 0, b2, nullptr, nullptr };
        sgemm<0, 64><<<dim3(1, M_ROWS / 64, 1), 256>>>(p);
    }
    proj_kernel<<<M_ROWS, 256>>>(xv2, inputs, proj, qproj);

    // g12 = proj @ [gw1 | gw2]   M=16384 N=256 K=272
    {
        GemmP p = { proj, gwT, g12, DHP, DHP, DHP, 256, 0, 0, 0, 0, nullptr, nullptr, nullptr };
        sgemm<1, 128><<<dim3(2, M_ROWS / 128, 1), 256>>>(p);
    }
    transpose_g1<<<dim3(TT / 32, DGC / 32, BB), dim3(32, 8)>>>(g12, g1T);

    // similarity -> E (tile-skipped) + fused denom atomics   K=272
    {
        GemmP p = { qproj, proj, E, DHP, DHP, DHP, TT,
                    (long)TT * DHP, (long)TT * DHP, (long)TT * TT, 0,
                    nullptr, seq, denom };
        sgemm<2, 128><<<dim3(TT / 128, TT / 128, BB), 256>>>(p);
    }
    // x1 raw partials = E @ g1T, split-K(2), K clamped to ceil16(L)
    {
        GemmP p = { E, g1T, x1p, TT, TT, TT, DGC,
                    (long)TT * TT, (long)DGC * TT, (long)TT * DGC,
                    (long)M_ROWS * DGC, nullptr, seq, nullptr };
        sgemm<3, 128><<<dim3(2, TT / 128, BB), 256>>>(p);
    }
    // x2 = leaky(disadj @ g2) via windowed exponential scan
    scan_kernel<<<dim3(BB, TT / SC), DGC>>>(g12, x2);

    // frame_prob: combine split-K partials, /denom, leaky, classifier dot
    frame_kernel<<<M_ROWS / 8, 256>>>(x1p, x2, denom, seq, cls_w, cls_b, frame, out);
    clas_kernel<<<BB, 1024>>>(frame, seq, out);
}

// round 16
// speedup vs baseline: 1.4720x; 1.1551x over previous
#include <cuda_runtime.h>
#include <math.h>

#define BB 8
#define TT 2048
#define M_ROWS (BB*TT)   /* 16384 */
#define DVC 1024
#define DAC 128
#define IN_C 1152
#define D1C 512
#define D2C 128
#define DHP 272          /* 257 padded to mult of 16 */
#define DGC 128

typedef unsigned long long u64;

/* ---------------- scratch (static device globals; no allocs) ---------------- */
__device__ float g_y1[M_ROWS * D1C];
__device__ float g_xv2[M_ROWS * D2C];
__device__ float g_proj[M_ROWS * DHP];
__device__ float g_qproj[M_ROWS * DHP];
__device__ float g_gwT[256 * DHP];
__device__ float g_g12[M_ROWS * 256];
__device__ float g_g1T[BB * DGC * TT];
__device__ float g_E[(size_t)BB * TT * TT]; // 134 MB
__device__ float g_denom[M_ROWS];
__device__ float g_x1p[2 * M_ROWS * DGC];   // adj split-K raw partials
__device__ float g_x2[M_ROWS * DGC];
__device__ float g_frame[M_ROWS];

/* ---------------- packed f32x2 helpers (Blackwell FFMA2) ---------------- */
__device__ __forceinline__ void ffma2(u64 &d, u64 a, u64 b) {
    asm("fma.rn.f32x2 %0, %1, %2, %0;" : "+l"(d) : "l"(a), "l"(b));
}
__device__ __forceinline__ u64 pack2(float x) {
    u64 r; asm("mov.b64 %0, {%1, %1};" : "=l"(r) : "f"(x)); return r;
}
__device__ __forceinline__ float2 unpk(u64 v) {
    float2 r; asm("mov.b64 {%0, %1}, %2;" : "=f"(r.x), "=f"(r.y) : "l"(v)); return r;
}

/* -------- generic 128x128 SGEMM, K-chunk 16, C = A[M,K] * B[N,K]^T -------- */
struct GemmP {
    const float* A; const float* Bm; float* C;
    int K, lda, ldb, ldc;
    long aS, bS, cS;            // per-blockIdx.z strides
    long splitStride;           // MODE3: offset between K-split partial buffers
    const float* bias;
    const int* seq;
};

// MODE 0: C = leaky(acc + bias[n])
// MODE 1: C = acc
// MODE 3: raw adj matmul partials, split-K over gridDim.x, K clamped to ceil16(L)
template <int MODE>
__global__ __launch_bounds__(256, 2) void sgemm(GemmP p) {
    const int z = blockIdx.z;
    const int rowBase = blockIdx.y << 7;
    int colBase, split;
    if (MODE == 3) { colBase = 0; split = blockIdx.x; }
    else           { colBase = blockIdx.x << 7; split = 0; }

    int L = 0;
    if (MODE == 3) {
        L = p.seq[z];
        if (rowBase >= L) return;                 // output rows masked
    }

    int k_begin = 0, k_end = p.K >> 4;      // chunks of 16
    if (MODE == 3) {
        const int nk_eff = (L + 15) >> 4;   // E cols >= ceil16(L) are zero
        const int half   = (nk_eff + 1) >> 1;
        k_begin = split ? half : 0;
        k_end   = split ? nk_eff : half;
    }

    __shared__ float As[2][16][128];
    __shared__ float Bs[2][16][128];
    const float* A  = p.A  + (long)z * p.aS;
    const float* Bm = p.Bm + (long)z * p.bS;
    float*       C  = p.C  + (long)z * p.cS + (long)split * p.splitStride;
    const int tid = threadIdx.x;
    const int tx = tid & 15, ty = tid >> 4;
    const int lr = tid >> 1;
    const int lc = (tid & 1) << 3;          // 0 or 8
    const float* aPtr = A  + (long)(rowBase + lr) * p.lda + lc;
    const float* bPtr = Bm + (long)(colBase + lr) * p.ldb + lc;

    u64 acc[8][4];
#pragma unroll
    for (int i = 0; i < 8; i++)
#pragma unroll
        for (int j = 0; j < 4; j++) acc[i][j] = 0ULL;

    // prologue: stage first chunk
    float4 av0 = *(const float4*)(aPtr + (k_begin << 4));
    float4 av1 = *(const float4*)(aPtr + (k_begin << 4) + 4);
    float4 bv0 = *(const float4*)(bPtr + (k_begin << 4));
    float4 bv1 = *(const float4*)(bPtr + (k_begin << 4) + 4);
    As[0][lc + 0][lr] = av0.x; As[0][lc + 1][lr] = av0.y;
    As[0][lc + 2][lr] = av0.z; As[0][lc + 3][lr] = av0.w;
    As[0][lc + 4][lr] = av1.x; As[0][lc + 5][lr] = av1.y;
    As[0][lc + 6][lr] = av1.z; As[0][lc + 7][lr] = av1.w;
    Bs[0][lc + 0][lr] = bv0.x; Bs[0][lc + 1][lr] = bv0.y;
    Bs[0][lc + 2][lr] = bv0.z; Bs[0][lc + 3][lr] = bv0.w;
    Bs[0][lc + 4][lr] = bv1.x; Bs[0][lc + 5][lr] = bv1.y;
    Bs[0][lc + 6][lr] = bv1.z; Bs[0][lc + 7][lr] = bv1.w;
    __syncthreads();

    for (int t = k_begin; t < k_end; t++) {
        const int cur = (t - k_begin) & 1;
        if (t + 1 < k_end) {
            av0 = *(const float4*)(aPtr + ((t + 1) << 4));
            av1 = *(const float4*)(aPtr + ((t + 1) << 4) + 4);
            bv0 = *(const float4*)(bPtr + ((t + 1) << 4));
            bv1 = *(const float4*)(bPtr + ((t + 1) << 4) + 4);
        }
#pragma unroll
        for (int kk = 0; kk < 16; kk++) {
            float4 a0 = *(const float4*)&As[cur][kk][ty << 3];
            float4 a1 = *(const float4*)&As[cur][kk][(ty << 3) + 4];
            ulonglong2 q0 = *(const ulonglong2*)&Bs[cur][kk][tx << 3];
            ulonglong2 q1 = *(const ulonglong2*)&Bs[cur][kk][(tx << 3) + 4];
            const u64 bb0 = q0.x, bb1 = q0.y, bb2 = q1.x, bb3 = q1.y;
            float aa[8] = {a0.x, a0.y, a0.z, a0.w, a1.x, a1.y, a1.z, a1.w};
#pragma unroll
            for (int i = 0; i < 8; i++) {
                u64 a2 = pack2(aa[i]);
                ffma2(acc[i][0], a2, bb0);
                ffma2(acc[i][1], a2, bb1);
                ffma2(acc[i][2], a2, bb2);
                ffma2(acc[i][3], a2, bb3);
            }
        }
        if (t + 1 < k_end) {
            const int nxt = cur ^ 1;
            As[nxt][lc + 0][lr] = av0.x; As[nxt][lc + 1][lr] = av0.y;
            As[nxt][lc + 2][lr] = av0.z; As[nxt][lc + 3][lr] = av0.w;
            As[nxt][lc + 4][lr] = av1.x; As[nxt][lc + 5][lr] = av1.y;
            As[nxt][lc + 6][lr] = av1.z; As[nxt][lc + 7][lr] = av1.w;
            Bs[nxt][lc + 0][lr] = bv0.x; Bs[nxt][lc + 1][lr] = bv0.y;
            Bs[nxt][lc + 2][lr] = bv0.z; Bs[nxt][lc + 3][lr] = bv0.w;
            Bs[nxt][lc + 4][lr] = bv1.x; Bs[nxt][lc + 5][lr] = bv1.y;
            Bs[nxt][lc + 6][lr] = bv1.z; Bs[nxt][lc + 7][lr] = bv1.w;
            __syncthreads();
        }
    }

#pragma unroll
    for (int i = 0; i < 8; i++) {
        const int m = rowBase + (ty << 3) + i;
        float vals[8];
#pragma unroll
        for (int pq = 0; pq < 4; pq++) {
            float2 f = unpk(acc[i][pq]);
            vals[2 * pq] = f.x; vals[2 * pq + 1] = f.y;
        }
        if (MODE == 0) {
#pragma unroll
            for (int j8 = 0; j8 < 8; j8++) {
                float v = vals[j8] + p.bias[colBase + (tx << 3) + j8];
                vals[j8] = (v >= 0.f) ? v : 0.01f * v;
            }
        }
        float4* dst = (float4*)&C[(long)m * p.ldc + colBase + (tx << 3)];
        dst[0] = make_float4(vals[0], vals[1], vals[2], vals[3]);
        dst[1] = make_float4(vals[4], vals[5], vals[6], vals[7]);
    }
}

/* -------- symmetric similarity kernel: upper-triangle tiles, K=272 -------- */
struct SimP {
    const float* qproj; const float* proj; float* E; const int* seq;
};

__global__ __launch_bounds__(256, 2) void sim_kernel(SimP p) {
    // map linear tile index -> (ti, tj) with ti <= tj  (16x16 tile grid)
    int rem = blockIdx.x, ti = 0, rowlen = 16;
    while (rem >= rowlen) { rem -= rowlen; ti++; rowlen--; }
    const int tj = ti + rem;

    const int z = blockIdx.z;
    const int L = p.seq[z];
    const int colBase = tj << 7;
    if (colBase >= L) return;                 // implies rowBase < L too (ti<=tj)
    const int rowBase = ti << 7;

    __shared__ float As[2][16][128];
    __shared__ float Bs[2][16][128];
    const float* A  = p.qproj + (long)z * TT * DHP;
    const float* Bm = p.proj  + (long)z * TT * DHP;
    float*       E  = p.E + (size_t)z * TT * TT;
    const int tid = threadIdx.x;
    const int tx = tid & 15, ty = tid >> 4;
    const int lr = tid >> 1;
    const int lc = (tid & 1) << 3;
    const float* aPtr = A  + (long)(rowBase + lr) * DHP + lc;
    const float* bPtr = Bm + (long)(colBase + lr) * DHP + lc;

    u64 acc[8][4];
#pragma unroll
    for (int i = 0; i < 8; i++)
#pragma unroll
        for (int j = 0; j < 4; j++) acc[i][j] = 0ULL;

    float4 av0 = *(const float4*)(aPtr);
    float4 av1 = *(const float4*)(aPtr + 4);
    float4 bv0 = *(const float4*)(bPtr);
    float4 bv1 = *(const float4*)(bPtr + 4);
    As[0][lc + 0][lr] = av0.x; As[0][lc + 1][lr] = av0.y;
    As[0][lc + 2][lr] = av0.z; As[0][lc + 3][lr] = av0.w;
    As[0][lc + 4][lr] = av1.x; As[0][lc + 5][lr] = av1.y;
    As[0][lc + 6][lr] = av1.z; As[0][lc + 7][lr] = av1.w;
    Bs[0][lc + 0][lr] = bv0.x; Bs[0][lc + 1][lr] = bv0.y;
    Bs[0][lc + 2][lr] = bv0.z; Bs[0][lc + 3][lr] = bv0.w;
    Bs[0][lc + 4][lr] = bv1.x; Bs[0][lc + 5][lr] = bv1.y;
    Bs[0][lc + 6][lr] = bv1.z; Bs[0][lc + 7][lr] = bv1.w;
    __syncthreads();

    const int k_end = DHP >> 4;   // 17
    for (int t = 0; t < k_end; t++) {
        const int cur = t & 1;
        if (t + 1 < k_end) {
            av0 = *(const float4*)(aPtr + ((t + 1) << 4));
            av1 = *(const float4*)(aPtr + ((t + 1) << 4) + 4);
            bv0 = *(const float4*)(bPtr + ((t + 1) << 4));
            bv1 = *(const float4*)(bPtr + ((t + 1) << 4) + 4);
        }
#pragma unroll
        for (int kk = 0; kk < 16; kk++) {
            float4 a0 = *(const float4*)&As[cur][kk][ty << 3];
            float4 a1 = *(const float4*)&As[cur][kk][(ty << 3) + 4];
            ulonglong2 q0 = *(const ulonglong2*)&Bs[cur][kk][tx << 3];
            ulonglong2 q1 = *(const ulonglong2*)&Bs[cur][kk][(tx << 3) + 4];
            const u64 bb0 = q0.x, bb1 = q0.y, bb2 = q1.x, bb3 = q1.y;
            float aa[8] = {a0.x, a0.y, a0.z, a0.w, a1.x, a1.y, a1.z, a1.w};
#pragma unroll
            for (int i = 0; i < 8; i++) {
                u64 a2 = pack2(aa[i]);
                ffma2(acc[i][0], a2, bb0);
                ffma2(acc[i][1], a2, bb1);
                ffma2(acc[i][2], a2, bb2);
                ffma2(acc[i][3], a2, bb3);
            }
        }
        if (t + 1 < k_end) {
            const int nxt = cur ^ 1;
            As[nxt][lc + 0][lr] = av0.x; As[nxt][lc + 1][lr] = av0.y;
            As[nxt][lc + 2][lr] = av0.z; As[nxt][lc + 3][lr] = av0.w;
            As[nxt][lc + 4][lr] = av1.x; As[nxt][lc + 5][lr] = av1.y;
            As[nxt][lc + 6][lr] = av1.z; As[nxt][lc + 7][lr] = av1.w;
            Bs[nxt][lc + 0][lr] = bv0.x; Bs[nxt][lc + 1][lr] = bv0.y;
            Bs[nxt][lc + 2][lr] = bv0.z; Bs[nxt][lc + 3][lr] = bv0.w;
            Bs[nxt][lc + 4][lr] = bv1.x; Bs[nxt][lc + 5][lr] = bv1.y;
            Bs[nxt][lc + 6][lr] = bv1.z; Bs[nxt][lc + 7][lr] = bv1.w;
            __syncthreads();
        }
    }

    /* epilogue in two j-halves to bound live registers */
    const bool offd = (ti != tj);
#pragma unroll
    for (int h = 0; h < 2; h++) {
        float vals[8][4];   // [i][j within half]
#pragma unroll
        for (int i = 0; i < 8; i++) {
#pragma unroll
            for (int pq = 0; pq < 2; pq++) {
                float2 f = unpk(acc[i][h * 2 + pq]);
                vals[i][2 * pq] = f.x; vals[i][2 * pq + 1] = f.y;
            }
#pragma unroll
            for (int jj = 0; jj < 4; jj++) {
                const int n = colBase + (tx << 3) + h * 4 + jj;
                float v = vals[i][jj];
                float e;
                if (n >= L) e = 0.f;
                else {
                    float xy = -v;
                    if (xy > 1.03f) e = 1.0f;  // thr=0 -> exp(0)=1 (bit-exact)
                    else {
                        xy = fmaxf(xy, 1.0f);
                        float w  = xy + sqrtf(xy * xy - 1.0f + 1e-7f);
                        float x2v = 1.0f / w;
                        e = (x2v > 0.8f) ? expf(x2v) : 1.0f;
                    }
                }
                vals[i][jj] = e;
            }
            // normal tile write: E[m][n..n+3]
            const int m = rowBase + (ty << 3) + i;
            *(float4*)&E[(size_t)m * TT + colBase + (tx << 3) + h * 4] =
                make_float4(vals[i][0], vals[i][1], vals[i][2], vals[i][3]);
        }
        if (offd) {
            // transposed tile write: for each n in this half, E[n][rowBase+ty*8 .. +7]
#pragma unroll
            for (int jj = 0; jj < 4; jj++) {
                const int n = colBase + (tx << 3) + h * 4 + jj;
                float* dst = &E[(size_t)n * TT + rowBase + (ty << 3)];
                *(float4*)(dst)     = make_float4(vals[0][jj], vals[1][jj],
                                                  vals[2][jj], vals[3][jj]);
                *(float4*)(dst + 4) = make_float4(vals[4][jj], vals[5][jj],
                                                  vals[6][jj], vals[7][jj]);
            }
        }
    }
}

/* ---------------- small kernels ---------------- */
__global__ void prep_gwT(const float* gw1, const float* gw2, float* gwT) {
    int idx = blockIdx.x * 256 + threadIdx.x;
    if (idx >= 256 * DHP) return;
    int r = idx / DHP, k = idx % DHP;
    float v = 0.f;
    if (k < 257) v = (r < 128) ? gw1[k * 128 + r] : gw2[k * 128 + (r - 128)];
    gwT[idx] = v;
}

__global__ void proj_kernel(const float* xv2, const float* inputs,
                            float* proj, float* qproj) {
    const int row = blockIdx.x;
    const int tid = threadIdx.x;  // 256
    float x = (tid < 128) ? xv2[row * 128 + tid]
                          : inputs[(long)row * IN_C + DVC + (tid - 128)];
    float ss = x * x;
    for (int o = 16; o > 0; o >>= 1) ss += __shfl_down_sync(0xffffffffu, ss, o);
    __shared__ float red[8];
    if ((tid & 31) == 0) red[tid >> 5] = ss;
    __syncthreads();
    __shared__ float nrm;
    if (tid == 0) {
        float t = ((red[0] + red[1]) + (red[2] + red[3])) +
                  ((red[4] + red[5]) + (red[6] + red[7]));
        nrm = sqrtf(fmaxf(t, 1e-12f));
    }
    __syncthreads();
    float nn = nrm;
    float sh = sinhf(nn) / nn;
    float* pr = proj  + (long)row * DHP;
    float* qr = qproj + (long)row * DHP;
    float val = sh * x;
    pr[1 + tid] = val;
    qr[1 + tid] = val;
    if (tid == 0) { float ch = coshf(nn); pr[0] = ch; qr[0] = -ch; }
    if (tid < 15) { pr[257 + tid] = 0.f; qr[257 + tid] = 0.f; }
}

__global__ void transpose_g1(const float* g12, float* g1T) {
    __shared__ float tile[32][33];
    int b = blockIdx.z;
    int t0 = blockIdx.x * 32, n0 = blockIdx.y * 32;
    for (int r = threadIdx.y; r < 32; r += 8)
        tile[r][threadIdx.x] = g12[((long)(b * TT + t0 + r)) * 256 + n0 + threadIdx.x];
    __syncthreads();
    for (int r = threadIdx.y; r < 32; r += 8)
        g1T[(long)b * DGC * TT + (long)(n0 + r) * TT + t0 + threadIdx.x] = tile[threadIdx.x][r];
}

__global__ void rowsum_kernel(const float* E, const int* seq, float* denom) {
    const int row = blockIdx.x;
    const int b = row >> 11;
    const int m = row & (TT - 1);
    const int L = seq[b];
    if (m >= L) return;                     // denom unread for masked rows
    const int jmax = ((L + 127) >> 7) << 7; // only written tiles
    const float4* e = (const float4*)(E + (size_t)row * TT);
    float s = 0.f;
    for (int j = threadIdx.x; j < (jmax >> 2); j += 256) {
        float4 v = e[j];
        s += (v.x + v.y) + (v.z + v.w);
    }
    for (int o = 16; o > 0; o >>= 1) s += __shfl_down_sync(0xffffffffu, s, o);
    __shared__ float red[8];
    if ((threadIdx.x & 31) == 0) red[threadIdx.x >> 5] = s;
    __syncthreads();
    if (threadIdx.x == 0) {
        float t = ((red[0] + red[1]) + (red[2] + red[3])) +
                  ((red[4] + red[5]) + (red[6] + red[7]));
        denom[row] = t;
    }
}

// disadj @ y via windowed forward+backward exponential scan (r^128 ~ 4e-21)
#define SC 64
#define SHALO 128
__global__ void scan_kernel(const float* g12, float* x2) {
    const int b = blockIdx.x;
    const int c = blockIdx.y;
    const int ch = threadIdx.x;        // 128 channels
    const float r = 0.69220062755534635f;  // exp(-exp(-1))
    __shared__ float sf[SC][DGC];
    const int s = c * SC;
    int i0 = s - SHALO; if (i0 < 0) i0 = 0;
    float f = 0.f;
    for (int i = i0; i < s + SC; i++) {
        float y = g12[((long)(b * TT + i)) * 256 + 128 + ch];
        f = fmaf(r, f, y);
        if (i >= s) sf[i - s][ch] = f;
    }
    int i1 = s + SC + SHALO; if (i1 > TT) i1 = TT;
    float bk = 0.f;
    for (int i = i1 - 1; i >= s; i--) {
        float y = g12[((long)(b * TT + i)) * 256 + 128 + ch];
        bk = fmaf(r, bk, y);
        if (i < s + SC) {
            float v = sf[i - s][ch] + bk - y;
            v = (v >= 0.f) ? v : 0.01f * v;
            x2[((long)(b * TT + i)) * DGC + ch] = v;
        }
    }
}

__global__ void frame_kernel(const float* x1p, const float* x2,
                             const float* denom, const int* seq,
                             const float* cls_w, const float* cls_b,
                             float* frame, float* out) {
    int warp = threadIdx.x >> 5, lane = threadIdx.x & 31;
    int row = blockIdx.x * 8 + warp;
    const int b = row >> 11;           // row / TT
    const int m = row & (TT - 1);
    const int L = seq[b];
    float s = 0.f;
    if (m < L) {
        float inv = 1.0f / denom[row];
        const float* p0 = x1p + (size_t)row * DGC;
        const float* p1 = p0 + (size_t)M_ROWS * DGC;
        for (int d = lane; d < DGC; d += 32) {
            float v = (p0[d] + p1[d]) * inv;
            v = (v >= 0.f) ? v : 0.01f * v;
            float sg = (d == 0) ? -1.0f : 1.0f;
            s += sg * v * cls_w[d];
        }
    }
    const float* xr2 = x2 + (size_t)row * DGC;
    for (int d = lane; d < DGC; d += 32)
        s += xr2[d] * cls_w[DGC + d];
    for (int o = 16; o > 0; o >>= 1) s += __shfl_down_sync(0xffffffffu, s, o);
    if (lane == 0) {
        float v = 2.0f + 2.0f * s + cls_b[0];
        frame[row] = v;
        out[8 + row] = v;
    }
}

__global__ void clas_kernel(const float* frame, const int* seq_len, float* out) {
    __shared__ float s[TT];
    __shared__ float red[1024];
    const int b = blockIdx.x, tid = threadIdx.x;
    const int L = seq_len[b];
    for (int t = tid; t < TT; t += 1024)
        s[t] = (t < L) ? frame[b * TT + t] : -1e30f;
    __syncthreads();
    for (int size = 2; size <= TT; size <<= 1) {
        for (int stride = size >> 1; stride > 0; stride >>= 1) {
            for (int i = tid; i < TT; i += 1024) {
                int l = i ^ stride;
                if (l > i) {
                    float a = s[i], c = s[l];
                    bool desc = ((i & size) == 0);
                    if (desc ? (a < c) : (a > c)) { s[i] = c; s[l] = a; }
                }
            }
            __syncthreads();
        }
    }
    int k = L / 16 + 1;
    float ps = 0.f;
    for (int t = tid; t < k; t += 1024) ps += s[t];
    red[tid] = ps;
    __syncthreads();
    for (int st = 512; st > 0; st >>= 1) {
        if (tid < st) red[tid] += red[tid + st];
        __syncthreads();
    }
    if (tid == 0) {
        float m = red[0] / (float)k;
        out[b] = 1.0f / (1.0f + expf(-m));
    }
}

/* ---------------- host orchestration ---------------- */
extern "C" void kernel_launch(void* const* d_in, const int* in_sizes, int n_in,
                              void* d_out, int out_size) {
    const float* inputs = (const float*)d_in[0];
    const int*   seq    = (const int*)d_in[1];
    const float* w1     = (const float*)d_in[2];
    const float* b1     = (const float*)d_in[3];
    const float* w2     = (const float*)d_in[4];
    const float* b2     = (const float*)d_in[5];
    const float* gw1    = (const float*)d_in[6];
    const float* gw2    = (const float*)d_in[7];
    const float* cls_w  = (const float*)d_in[8];
    const float* cls_b  = (const float*)d_in[9];
    float* out = (float*)d_out;

    float *y1, *xv2, *proj, *qproj, *gwT, *g12, *g1T, *E, *denom, *x1p, *x2, *frame;
    cudaGetSymbolAddress((void**)&y1,    g_y1);
    cudaGetSymbolAddress((void**)&xv2,   g_xv2);
    cudaGetSymbolAddress((void**)&proj,  g_proj);
    cudaGetSymbolAddress((void**)&qproj, g_qproj);
    cudaGetSymbolAddress((void**)&gwT,   g_gwT);
    cudaGetSymbolAddress((void**)&g12,   g_g12);
    cudaGetSymbolAddress((void**)&g1T,   g_g1T);
    cudaGetSymbolAddress((void**)&E,     g_E);
    cudaGetSymbolAddress((void**)&denom, g_denom);
    cudaGetSymbolAddress((void**)&x1p,   g_x1p);
    cudaGetSymbolAddress((void**)&x2,    g_x2);
    cudaGetSymbolAddress((void**)&frame, g_frame);

    prep_gwT<<<(256 * DHP + 255) / 256, 256>>>(gw1, gw2, gwT);

    // GEMM1: y1 = leaky(inputs[:, :1024] @ w1^T + b1)   M=16384 N=512 K=1024
    {
        GemmP p = { inputs, w1, y1, DVC, IN_C, DVC, D1C, 0, 0, 0, 0, b1, nullptr };
        sgemm<0><<<dim3(D1C / 128, M_ROWS / 128, 1), 256>>>(p);
    }
    // GEMM2: xv2 = leaky(y1 @ w2^T + b2)   M=16384 N=128 K=512
    {
        GemmP p = { y1, w2, xv2, D1C, D1C, D1C, D2C, 0, 0, 0, 0, b2, nullptr };
        sgemm<0><<<dim3(1, M_ROWS / 128, 1), 256>>>(p);
    }
    proj_kernel<<<M_ROWS, 256>>>(xv2, inputs, proj, qproj);

    // g12 = proj @ [gw1 | gw2]   M=16384 N=256 K=272
    {
        GemmP p = { proj, gwT, g12, DHP, DHP, DHP, 256, 0, 0, 0, 0, nullptr, nullptr };
        sgemm<1><<<dim3(2, M_ROWS / 128, 1), 256>>>(p);
    }
    transpose_g1<<<dim3(TT / 32, DGC / 32, BB), dim3(32, 8)>>>(g12, g1T);

    // similarity -> E, symmetric upper-triangle tiles (mirror via register transpose)
    {
        SimP p = { qproj, proj, E, seq };
        sim_kernel<<<dim3(136, 1, BB), 256>>>(p);
    }
    // softmax denominators over written column span
    rowsum_kernel<<<M_ROWS, 256>>>(E, seq, denom);

    // x1 raw partials = E @ g1T, split-K(2), K clamped to ceil16(L)
    {
        GemmP p = { E, g1T, x1p, TT, TT, TT, DGC,
                    (long)TT * TT, (long)DGC * TT, (long)TT * DGC,
                    (long)M_ROWS * DGC, nullptr, seq };
        sgemm<3><<<dim3(2, TT / 128, BB), 256>>>(p);
    }
    // x2 = leaky(disadj @ g2) via windowed exponential scan
    scan_kernel<<<dim3(BB, TT / SC), DGC>>>(g12, x2);

    // frame_prob: combine split-K partials, /denom, leaky, classifier dot
    frame_kernel<<<M_ROWS / 8, 256>>>(x1p, x2, denom, seq, cls_w, cls_b, frame, out);
    clas_kernel<<<BB, 1024>>>(frame, seq, out);
}

// round 17
// speedup vs baseline: 1.5246x; 1.0358x over previous
#include <cuda_runtime.h>
#include <math.h>

#define BB 8
#define TT 2048
#define M_ROWS (BB*TT)   /* 16384 */
#define DVC 1024
#define DAC 128
#define IN_C 1152
#define D1C 512
#define D2C 128
#define DHP 272          /* 257 padded to mult of 16 */
#define DGC 128

typedef unsigned long long u64;

/* ---------------- scratch (static device globals; no allocs) ---------------- */
__device__ float g_y1[M_ROWS * D1C];
__device__ float g_xv2[M_ROWS * D2C];
__device__ float g_proj[M_ROWS * DHP];
__device__ float g_qproj[M_ROWS * DHP];
__device__ float g_gwT[256 * DHP];
__device__ float g_g12[M_ROWS * 256];
__device__ float g_E[(size_t)BB * TT * TT]; // 134 MB
__device__ float g_x1p[2 * M_ROWS * DGC];   // adj split-K raw partials
__device__ float g_denp[2 * M_ROWS];        // adj split-K denom partials
__device__ float g_x2[M_ROWS * DGC];
__device__ float g_frame[M_ROWS];

/* ---------------- packed f32x2 helpers (Blackwell FFMA2) ---------------- */
__device__ __forceinline__ void ffma2(u64 &d, u64 a, u64 b) {
    asm("fma.rn.f32x2 %0, %1, %2, %0;" : "+l"(d) : "l"(a), "l"(b));
}
__device__ __forceinline__ u64 pack2(float x) {
    u64 r; asm("mov.b64 %0, {%1, %1};" : "=l"(r) : "f"(x)); return r;
}
__device__ __forceinline__ float2 unpk(u64 v) {
    float2 r; asm("mov.b64 {%0, %1}, %2;" : "=f"(r.x), "=f"(r.y) : "l"(v)); return r;
}

/* -------- generic 128x128 SGEMM, K-chunk 16, C = A[M,K] * B[N,K]^T -------- */
struct GemmP {
    const float* A; const float* Bm; float* C;
    int K, lda, ldb, ldc;
    const float* bias;
};

// MODE 0: C = leaky(acc + bias[n]) ; MODE 1: C = acc
template <int MODE>
__global__ __launch_bounds__(256, 2) void sgemm(GemmP p) {
    const int rowBase = blockIdx.y << 7;
    const int colBase = blockIdx.x << 7;

    __shared__ float As[2][16][128];
    __shared__ float Bs[2][16][128];
    const int tid = threadIdx.x;
    const int tx = tid & 15, ty = tid >> 4;
    const int lr = tid >> 1;
    const int lc = (tid & 1) << 3;          // 0 or 8
    const float* aPtr = p.A  + (long)(rowBase + lr) * p.lda + lc;
    const float* bPtr = p.Bm + (long)(colBase + lr) * p.ldb + lc;
    const int k_end = p.K >> 4;

    u64 acc[8][4];
#pragma unroll
    for (int i = 0; i < 8; i++)
#pragma unroll
        for (int j = 0; j < 4; j++) acc[i][j] = 0ULL;

    float4 av0 = *(const float4*)(aPtr);
    float4 av1 = *(const float4*)(aPtr + 4);
    float4 bv0 = *(const float4*)(bPtr);
    float4 bv1 = *(const float4*)(bPtr + 4);
    As[0][lc + 0][lr] = av0.x; As[0][lc + 1][lr] = av0.y;
    As[0][lc + 2][lr] = av0.z; As[0][lc + 3][lr] = av0.w;
    As[0][lc + 4][lr] = av1.x; As[0][lc + 5][lr] = av1.y;
    As[0][lc + 6][lr] = av1.z; As[0][lc + 7][lr] = av1.w;
    Bs[0][lc + 0][lr] = bv0.x; Bs[0][lc + 1][lr] = bv0.y;
    Bs[0][lc + 2][lr] = bv0.z; Bs[0][lc + 3][lr] = bv0.w;
    Bs[0][lc + 4][lr] = bv1.x; Bs[0][lc + 5][lr] = bv1.y;
    Bs[0][lc + 6][lr] = bv1.z; Bs[0][lc + 7][lr] = bv1.w;
    __syncthreads();

    for (int t = 0; t < k_end; t++) {
        const int cur = t & 1;
        if (t + 1 < k_end) {
            av0 = *(const float4*)(aPtr + ((t + 1) << 4));
            av1 = *(const float4*)(aPtr + ((t + 1) << 4) + 4);
            bv0 = *(const float4*)(bPtr + ((t + 1) << 4));
            bv1 = *(const float4*)(bPtr + ((t + 1) << 4) + 4);
        }
#pragma unroll
        for (int kk = 0; kk < 16; kk++) {
            float4 a0 = *(const float4*)&As[cur][kk][ty << 3];
            float4 a1 = *(const float4*)&As[cur][kk][(ty << 3) + 4];
            ulonglong2 q0 = *(const ulonglong2*)&Bs[cur][kk][tx << 3];
            ulonglong2 q1 = *(const ulonglong2*)&Bs[cur][kk][(tx << 3) + 4];
            const u64 bb0 = q0.x, bb1 = q0.y, bb2 = q1.x, bb3 = q1.y;
            float aa[8] = {a0.x, a0.y, a0.z, a0.w, a1.x, a1.y, a1.z, a1.w};
#pragma unroll
            for (int i = 0; i < 8; i++) {
                u64 a2 = pack2(aa[i]);
                ffma2(acc[i][0], a2, bb0);
                ffma2(acc[i][1], a2, bb1);
                ffma2(acc[i][2], a2, bb2);
                ffma2(acc[i][3], a2, bb3);
            }
        }
        if (t + 1 < k_end) {
            const int nxt = cur ^ 1;
            As[nxt][lc + 0][lr] = av0.x; As[nxt][lc + 1][lr] = av0.y;
            As[nxt][lc + 2][lr] = av0.z; As[nxt][lc + 3][lr] = av0.w;
            As[nxt][lc + 4][lr] = av1.x; As[nxt][lc + 5][lr] = av1.y;
            As[nxt][lc + 6][lr] = av1.z; As[nxt][lc + 7][lr] = av1.w;
            Bs[nxt][lc + 0][lr] = bv0.x; Bs[nxt][lc + 1][lr] = bv0.y;
            Bs[nxt][lc + 2][lr] = bv0.z; Bs[nxt][lc + 3][lr] = bv0.w;
            Bs[nxt][lc + 4][lr] = bv1.x; Bs[nxt][lc + 5][lr] = bv1.y;
            Bs[nxt][lc + 6][lr] = bv1.z; Bs[nxt][lc + 7][lr] = bv1.w;
            __syncthreads();
        }
    }

#pragma unroll
    for (int i = 0; i < 8; i++) {
        const int m = rowBase + (ty << 3) + i;
        float vals[8];
#pragma unroll
        for (int pq = 0; pq < 4; pq++) {
            float2 f = unpk(acc[i][pq]);
            vals[2 * pq] = f.x; vals[2 * pq + 1] = f.y;
        }
        if (MODE == 0) {
#pragma unroll
            for (int j8 = 0; j8 < 8; j8++) {
                float v = vals[j8] + p.bias[colBase + (tx << 3) + j8];
                vals[j8] = (v >= 0.f) ? v : 0.01f * v;
            }
        }
        float4* dst = (float4*)&p.C[(long)m * p.ldc + colBase + (tx << 3)];
        dst[0] = make_float4(vals[0], vals[1], vals[2], vals[3]);
        dst[1] = make_float4(vals[4], vals[5], vals[6], vals[7]);
    }
}

/* -------- symmetric similarity kernel: upper-triangle tiles, K=272 -------- */
struct SimP {
    const float* qproj; const float* proj; float* E; const int* seq;
};

__global__ __launch_bounds__(256, 2) void sim_kernel(SimP p) {
    // map linear tile index -> (ti, tj) with ti <= tj  (16x16 tile grid)
    int rem = blockIdx.x, ti = 0, rowlen = 16;
    while (rem >= rowlen) { rem -= rowlen; ti++; rowlen--; }
    const int tj = ti + rem;

    const int z = blockIdx.z;
    const int L = p.seq[z];
    const int colBase = tj << 7;
    if (colBase >= L) return;                 // implies rowBase < L too (ti<=tj)
    const int rowBase = ti << 7;

    __shared__ float As[2][16][128];
    __shared__ float Bs[2][16][128];
    const float* A  = p.qproj + (long)z * TT * DHP;
    const float* Bm = p.proj  + (long)z * TT * DHP;
    float*       E  = p.E + (size_t)z * TT * TT;
    const int tid = threadIdx.x;
    const int tx = tid & 15, ty = tid >> 4;
    const int lr = tid >> 1;
    const int lc = (tid & 1) << 3;
    const float* aPtr = A  + (long)(rowBase + lr) * DHP + lc;
    const float* bPtr = Bm + (long)(colBase + lr) * DHP + lc;

    u64 acc[8][4];
#pragma unroll
    for (int i = 0; i < 8; i++)
#pragma unroll
        for (int j = 0; j < 4; j++) acc[i][j] = 0ULL;

    float4 av0 = *(const float4*)(aPtr);
    float4 av1 = *(const float4*)(aPtr + 4);
    float4 bv0 = *(const float4*)(bPtr);
    float4 bv1 = *(const float4*)(bPtr + 4);
    As[0][lc + 0][lr] = av0.x; As[0][lc + 1][lr] = av0.y;
    As[0][lc + 2][lr] = av0.z; As[0][lc + 3][lr] = av0.w;
    As[0][lc + 4][lr] = av1.x; As[0][lc + 5][lr] = av1.y;
    As[0][lc + 6][lr] = av1.z; As[0][lc + 7][lr] = av1.w;
    Bs[0][lc + 0][lr] = bv0.x; Bs[0][lc + 1][lr] = bv0.y;
    Bs[0][lc + 2][lr] = bv0.z; Bs[0][lc + 3][lr] = bv0.w;
    Bs[0][lc + 4][lr] = bv1.x; Bs[0][lc + 5][lr] = bv1.y;
    Bs[0][lc + 6][lr] = bv1.z; Bs[0][lc + 7][lr] = bv1.w;
    __syncthreads();

    const int k_end = DHP >> 4;   // 17
    for (int t = 0; t < k_end; t++) {
        const int cur = t & 1;
        if (t + 1 < k_end) {
            av0 = *(const float4*)(aPtr + ((t + 1) << 4));
            av1 = *(const float4*)(aPtr + ((t + 1) << 4) + 4);
            bv0 = *(const float4*)(bPtr + ((t + 1) << 4));
            bv1 = *(const float4*)(bPtr + ((t + 1) << 4) + 4);
        }
#pragma unroll
        for (int kk = 0; kk < 16; kk++) {
            float4 a0 = *(const float4*)&As[cur][kk][ty << 3];
            float4 a1 = *(const float4*)&As[cur][kk][(ty << 3) + 4];
            ulonglong2 q0 = *(const ulonglong2*)&Bs[cur][kk][tx << 3];
            ulonglong2 q1 = *(const ulonglong2*)&Bs[cur][kk][(tx << 3) + 4];
            const u64 bb0 = q0.x, bb1 = q0.y, bb2 = q1.x, bb3 = q1.y;
            float aa[8] = {a0.x, a0.y, a0.z, a0.w, a1.x, a1.y, a1.z, a1.w};
#pragma unroll
            for (int i = 0; i < 8; i++) {
                u64 a2 = pack2(aa[i]);
                ffma2(acc[i][0], a2, bb0);
                ffma2(acc[i][1], a2, bb1);
                ffma2(acc[i][2], a2, bb2);
                ffma2(acc[i][3], a2, bb3);
            }
        }
        if (t + 1 < k_end) {
            const int nxt = cur ^ 1;
            As[nxt][lc + 0][lr] = av0.x; As[nxt][lc + 1][lr] = av0.y;
            As[nxt][lc + 2][lr] = av0.z; As[nxt][lc + 3][lr] = av0.w;
            As[nxt][lc + 4][lr] = av1.x; As[nxt][lc + 5][lr] = av1.y;
            As[nxt][lc + 6][lr] = av1.z; As[nxt][lc + 7][lr] = av1.w;
            Bs[nxt][lc + 0][lr] = bv0.x; Bs[nxt][lc + 1][lr] = bv0.y;
            Bs[nxt][lc + 2][lr] = bv0.z; Bs[nxt][lc + 3][lr] = bv0.w;
            Bs[nxt][lc + 4][lr] = bv1.x; Bs[nxt][lc + 5][lr] = bv1.y;
            Bs[nxt][lc + 6][lr] = bv1.z; Bs[nxt][lc + 7][lr] = bv1.w;
            __syncthreads();
        }
    }

    /* epilogue in two j-halves to bound live registers */
    const bool offd = (ti != tj);
#pragma unroll
    for (int h = 0; h < 2; h++) {
        float vals[8][4];   // [i][j within half]
#pragma unroll
        for (int i = 0; i < 8; i++) {
#pragma unroll
            for (int pq = 0; pq < 2; pq++) {
                float2 f = unpk(acc[i][h * 2 + pq]);
                vals[i][2 * pq] = f.x; vals[i][2 * pq + 1] = f.y;
            }
#pragma unroll
            for (int jj = 0; jj < 4; jj++) {
                const int n = colBase + (tx << 3) + h * 4 + jj;
                float v = vals[i][jj];
                float e;
                if (n >= L) e = 0.f;
                else {
                    float xy = -v;
                    if (xy > 1.03f) e = 1.0f;  // thr=0 -> exp(0)=1 (bit-exact)
                    else {
                        xy = fmaxf(xy, 1.0f);
                        float w  = xy + sqrtf(xy * xy - 1.0f + 1e-7f);
                        float x2v = 1.0f / w;
                        e = (x2v > 0.8f) ? expf(x2v) : 1.0f;
                    }
                }
                vals[i][jj] = e;
            }
            // normal tile write: E[m][n..n+3]
            const int m = rowBase + (ty << 3) + i;
            *(float4*)&E[(size_t)m * TT + colBase + (tx << 3) + h * 4] =
                make_float4(vals[i][0], vals[i][1], vals[i][2], vals[i][3]);
        }
        if (offd) {
            // transposed tile write: for each n in this half, E[n][rowBase+ty*8 .. +7]
#pragma unroll
            for (int jj = 0; jj < 4; jj++) {
                const int n = colBase + (tx << 3) + h * 4 + jj;
                float* dst = &E[(size_t)n * TT + rowBase + (ty << 3)];
                *(float4*)(dst)     = make_float4(vals[0][jj], vals[1][jj],
                                                  vals[2][jj], vals[3][jj]);
                *(float4*)(dst + 4) = make_float4(vals[4][jj], vals[5][jj],
                                                  vals[6][jj], vals[7][jj]);
            }
        }
    }
}

/* -------- adj kernel: x1 partials = E @ g1 (B straight from g12),
           fused per-split softmax-denominator partials -------- */
struct AdjP {
    const float* E; const float* g12; float* x1p; float* denp; const int* seq;
};

__global__ __launch_bounds__(256, 2) void adj_kernel(AdjP p) {
    const int z = blockIdx.z;
    const int rowBase = blockIdx.y << 7;
    const int split = blockIdx.x;
    const int L = p.seq[z];
    if (rowBase >= L) return;                 // output rows masked

    const int nk_eff = (L + 15) >> 4;         // E cols >= ceil16(L) are zero
    const int half   = (nk_eff + 1) >> 1;
    const int k_begin = split ? half : 0;
    const int k_end   = split ? nk_eff : half;

    const int tid = threadIdx.x;
    const int tx = tid & 15, ty = tid >> 4;
    const int lr = tid >> 1;
    const int lc = (tid & 1) << 3;            // 0 or 8
    const long bTT = (long)z * TT;

    if (k_begin >= k_end) {                   // degenerate split: zero outputs
        if ((tid & 1) == 0)
            p.denp[(size_t)split * M_ROWS + bTT + rowBase + lr] = 0.f;
#pragma unroll
        for (int i = 0; i < 8; i++) {
            float* dst = &p.x1p[((size_t)split * M_ROWS + bTT + rowBase +
                                 (ty << 3) + i) * DGC + (tx << 3)];
            *(float4*)(dst)     = make_float4(0.f, 0.f, 0.f, 0.f);
            *(float4*)(dst + 4) = make_float4(0.f, 0.f, 0.f, 0.f);
        }
        return;
    }

    __shared__ float As[2][16][128];
    __shared__ float Bs[2][16][128];
    const float* aPtr = p.E + ((size_t)z * TT + rowBase + lr) * TT + lc;
    // B staging straight from g12: Bs[kk][n] = g12[bTT + k][n]; coalesced rows
    const int brow = tid >> 4;                // kk 0..15
    const int bcol = (tid & 15) << 3;         // n
    const float* gBase = p.g12 + (bTT + brow) * 256 + bcol;

    u64 acc[8][4];
#pragma unroll
    for (int i = 0; i < 8; i++)
#pragma unroll
        for (int j = 0; j < 4; j++) acc[i][j] = 0ULL;

    float rs = 0.f;   // partial row-sum of staged E values (row = lr)

    // prologue: stage chunk k_begin
    float4 av0 = *(const float4*)(aPtr + (k_begin << 4));
    float4 av1 = *(const float4*)(aPtr + (k_begin << 4) + 4);
    rs += ((av0.x + av0.y) + (av0.z + av0.w)) +
          ((av1.x + av1.y) + (av1.z + av1.w));
    float4 bv0 = *(const float4*)(gBase + (long)(k_begin << 4) * 256);
    float4 bv1 = *(const float4*)(gBase + (long)(k_begin << 4) * 256 + 4);
    As[0][lc + 0][lr] = av0.x; As[0][lc + 1][lr] = av0.y;
    As[0][lc + 2][lr] = av0.z; As[0][lc + 3][lr] = av0.w;
    As[0][lc + 4][lr] = av1.x; As[0][lc + 5][lr] = av1.y;
    As[0][lc + 6][lr] = av1.z; As[0][lc + 7][lr] = av1.w;
    *(float4*)&Bs[0][brow][bcol]     = bv0;
    *(float4*)&Bs[0][brow][bcol + 4] = bv1;
    __syncthreads();

    for (int t = k_begin; t < k_end; t++) {
        const int cur = (t - k_begin) & 1;
        if (t + 1 < k_end) {
            av0 = *(const float4*)(aPtr + ((t + 1) << 4));
            av1 = *(const float4*)(aPtr + ((t + 1) << 4) + 4);
            rs += ((av0.x + av0.y) + (av0.z + av0.w)) +
                  ((av1.x + av1.y) + (av1.z + av1.w));
            bv0 = *(const float4*)(gBase + (long)((t + 1) << 4) * 256);
            bv1 = *(const float4*)(gBase + (long)((t + 1) << 4) * 256 + 4);
        }
#pragma unroll
        for (int kk = 0; kk < 16; kk++) {
            float4 a0 = *(const float4*)&As[cur][kk][ty << 3];
            float4 a1 = *(const float4*)&As[cur][kk][(ty << 3) + 4];
            ulonglong2 q0 = *(const ulonglong2*)&Bs[cur][kk][tx << 3];
            ulonglong2 q1 = *(const ulonglong2*)&Bs[cur][kk][(tx << 3) + 4];
            const u64 bb0 = q0.x, bb1 = q0.y, bb2 = q1.x, bb3 = q1.y;
            float aa[8] = {a0.x, a0.y, a0.z, a0.w, a1.x, a1.y, a1.z, a1.w};
#pragma unroll
            for (int i = 0; i < 8; i++) {
                u64 a2 = pack2(aa[i]);
                ffma2(acc[i][0], a2, bb0);
                ffma2(acc[i][1], a2, bb1);
                ffma2(acc[i][2], a2, bb2);
                ffma2(acc[i][3], a2, bb3);
            }
        }
        if (t + 1 < k_end) {
            const int nxt = cur ^ 1;
            As[nxt][lc + 0][lr] = av0.x; As[nxt][lc + 1][lr] = av0.y;
            As[nxt][lc + 2][lr] = av0.z; As[nxt][lc + 3][lr] = av0.w;
            As[nxt][lc + 4][lr] = av1.x; As[nxt][lc + 5][lr] = av1.y;
            As[nxt][lc + 6][lr] = av1.z; As[nxt][lc + 7][lr] = av1.w;
            *(float4*)&Bs[nxt][brow][bcol]     = bv0;
            *(float4*)&Bs[nxt][brow][bcol + 4] = bv1;
            __syncthreads();
        }
    }

    // denominator partial: combine the two staging threads of row lr
    rs += __shfl_xor_sync(0xffffffffu, rs, 1);
    if ((tid & 1) == 0)
        p.denp[(size_t)split * M_ROWS + bTT + rowBase + lr] = rs;

#pragma unroll
    for (int i = 0; i < 8; i++) {
        const int m = rowBase + (ty << 3) + i;
        float vals[8];
#pragma unroll
        for (int pq = 0; pq < 4; pq++) {
            float2 f = unpk(acc[i][pq]);
            vals[2 * pq] = f.x; vals[2 * pq + 1] = f.y;
        }
        float* dst = &p.x1p[((size_t)split * M_ROWS + bTT + m) * DGC + (tx << 3)];
        *(float4*)(dst)     = make_float4(vals[0], vals[1], vals[2], vals[3]);
        *(float4*)(dst + 4) = make_float4(vals[4], vals[5], vals[6], vals[7]);
    }
}

/* ---------------- small kernels ---------------- */
__global__ void prep_gwT(const float* gw1, const float* gw2, float* gwT) {
    int idx = blockIdx.x * 256 + threadIdx.x;
    if (idx >= 256 * DHP) return;
    int r = idx / DHP, k = idx % DHP;
    float v = 0.f;
    if (k < 257) v = (r < 128) ? gw1[k * 128 + r] : gw2[k * 128 + (r - 128)];
    gwT[idx] = v;
}

__global__ void proj_kernel(const float* xv2, const float* inputs,
                            float* proj, float* qproj) {
    const int row = blockIdx.x;
    const int tid = threadIdx.x;  // 256
    float x = (tid < 128) ? xv2[row * 128 + tid]
                          : inputs[(long)row * IN_C + DVC + (tid - 128)];
    float ss = x * x;
    for (int o = 16; o > 0; o >>= 1) ss += __shfl_down_sync(0xffffffffu, ss, o);
    __shared__ float red[8];
    if ((tid & 31) == 0) red[tid >> 5] = ss;
    __syncthreads();
    __shared__ float nrm;
    if (tid == 0) {
        float t = ((red[0] + red[1]) + (red[2] + red[3])) +
                  ((red[4] + red[5]) + (red[6] + red[7]));
        nrm = sqrtf(fmaxf(t, 1e-12f));
    }
    __syncthreads();
    float nn = nrm;
    float sh = sinhf(nn) / nn;
    float* pr = proj  + (long)row * DHP;
    float* qr = qproj + (long)row * DHP;
    float val = sh * x;
    pr[1 + tid] = val;
    qr[1 + tid] = val;
    if (tid == 0) { float ch = coshf(nn); pr[0] = ch; qr[0] = -ch; }
    if (tid < 15) { pr[257 + tid] = 0.f; qr[257 + tid] = 0.f; }
}

// disadj @ y via windowed forward+backward exponential scan (r^128 ~ 4e-21)
#define SC 64
#define SHALO 128
__global__ void scan_kernel(const float* g12, float* x2) {
    const int b = blockIdx.x;
    const int c = blockIdx.y;
    const int ch = threadIdx.x;        // 128 channels
    const float r = 0.69220062755534635f;  // exp(-exp(-1))
    __shared__ float sf[SC][DGC];
    const int s = c * SC;
    int i0 = s - SHALO; if (i0 < 0) i0 = 0;
    float f = 0.f;
    for (int i = i0; i < s + SC; i++) {
        float y = g12[((long)(b * TT + i)) * 256 + 128 + ch];
        f = fmaf(r, f, y);
        if (i >= s) sf[i - s][ch] = f;
    }
    int i1 = s + SC + SHALO; if (i1 > TT) i1 = TT;
    float bk = 0.f;
    for (int i = i1 - 1; i >= s; i--) {
        float y = g12[((long)(b * TT + i)) * 256 + 128 + ch];
        bk = fmaf(r, bk, y);
        if (i < s + SC) {
            float v = sf[i - s][ch] + bk - y;
            v = (v >= 0.f) ? v : 0.01f * v;
            x2[((long)(b * TT + i)) * DGC + ch] = v;
        }
    }
}

__global__ void frame_kernel(const float* x1p, const float* x2,
                             const float* denp, const int* seq,
                             const float* cls_w, const float* cls_b,
                             float* frame, float* out) {
    int warp = threadIdx.x >> 5, lane = threadIdx.x & 31;
    int row = blockIdx.x * 8 + warp;
    const int b = row >> 11;           // row / TT
    const int m = row & (TT - 1);
    const int L = seq[b];
    float s = 0.f;
    if (m < L) {
        float inv = 1.0f / (denp[row] + denp[M_ROWS + row]);
        const float* p0 = x1p + (size_t)row * DGC;
        const float* p1 = p0 + (size_t)M_ROWS * DGC;
        for (int d = lane; d < DGC; d += 32) {
            float v = (p0[d] + p1[d]) * inv;
            v = (v >= 0.f) ? v : 0.01f * v;
            float sg = (d == 0) ? -1.0f : 1.0f;
            s += sg * v * cls_w[d];
        }
    }
    const float* xr2 = x2 + (size_t)row * DGC;
    for (int d = lane; d < DGC; d += 32)
        s += xr2[d] * cls_w[DGC + d];
    for (int o = 16; o > 0; o >>= 1) s += __shfl_down_sync(0xffffffffu, s, o);
    if (lane == 0) {
        float v = 2.0f + 2.0f * s + cls_b[0];
        frame[row] = v;
        out[8 + row] = v;
    }
}

__global__ void clas_kernel(const float* frame, const int* seq_len, float* out) {
    __shared__ float s[TT];
    __shared__ float red[1024];
    const int b = blockIdx.x, tid = threadIdx.x;
    const int L = seq_len[b];
    for (int t = tid; t < TT; t += 1024)
        s[t] = (t < L) ? frame[b * TT + t] : -1e30f;
    __syncthreads();
    for (int size = 2; size <= TT; size <<= 1) {
        for (int stride = size >> 1; stride > 0; stride >>= 1) {
            for (int i = tid; i < TT; i += 1024) {
                int l = i ^ stride;
                if (l > i) {
                    float a = s[i], c = s[l];
                    bool desc = ((i & size) == 0);
                    if (desc ? (a < c) : (a > c)) { s[i] = c; s[l] = a; }
                }
            }
            __syncthreads();
        }
    }
    int k = L / 16 + 1;
    float ps = 0.f;
    for (int t = tid; t < k; t += 1024) ps += s[t];
    red[tid] = ps;
    __syncthreads();
    for (int st = 512; st > 0; st >>= 1) {
        if (tid < st) red[tid] += red[tid + st];
        __syncthreads();
    }
    if (tid == 0) {
        float m = red[0] / (float)k;
        out[b] = 1.0f / (1.0f + expf(-m));
    }
}

/* ---------------- host orchestration ---------------- */
extern "C" void kernel_launch(void* const* d_in, const int* in_sizes, int n_in,
                              void* d_out, int out_size) {
    const float* inputs = (const float*)d_in[0];
    const int*   seq    = (const int*)d_in[1];
    const float* w1     = (const float*)d_in[2];
    const float* b1     = (const float*)d_in[3];
    const float* w2     = (const float*)d_in[4];
    const float* b2     = (const float*)d_in[5];
    const float* gw1    = (const float*)d_in[6];
    const float* gw2    = (const float*)d_in[7];
    const float* cls_w  = (const float*)d_in[8];
    const float* cls_b  = (const float*)d_in[9];
    float* out = (float*)d_out;

    float *y1, *xv2, *proj, *qproj, *gwT, *g12, *E, *x1p, *denp, *x2, *frame;
    cudaGetSymbolAddress((void**)&y1,    g_y1);
    cudaGetSymbolAddress((void**)&xv2,   g_xv2);
    cudaGetSymbolAddress((void**)&proj,  g_proj);
    cudaGetSymbolAddress((void**)&qproj, g_qproj);
    cudaGetSymbolAddress((void**)&gwT,   g_gwT);
    cudaGetSymbolAddress((void**)&g12,   g_g12);
    cudaGetSymbolAddress((void**)&E,     g_E);
    cudaGetSymbolAddress((void**)&x1p,   g_x1p);
    cudaGetSymbolAddress((void**)&denp,  g_denp);
    cudaGetSymbolAddress((void**)&x2,    g_x2);
    cudaGetSymbolAddress((void**)&frame, g_frame);

    prep_gwT<<<(256 * DHP + 255) / 256, 256>>>(gw1, gw2, gwT);

    // GEMM1: y1 = leaky(inputs[:, :1024] @ w1^T + b1)   M=16384 N=512 K=1024
    {
        GemmP p = { inputs, w1, y1, DVC, IN_C, DVC, D1C, b1 };
        sgemm<0><<<dim3(D1C / 128, M_ROWS / 128, 1), 256>>>(p);
    }
    // GEMM2: xv2 = leaky(y1 @ w2^T + b2)   M=16384 N=128 K=512
    {
        GemmP p = { y1, w2, xv2, D1C, D1C, D1C, D2C, b2 };
        sgemm<0><<<dim3(1, M_ROWS / 128, 1), 256>>>(p);
    }
    proj_kernel<<<M_ROWS, 256>>>(xv2, inputs, proj, qproj);

    // g12 = proj @ [gw1 | gw2]   M=16384 N=256 K=272
    {
        GemmP p = { proj, gwT, g12, DHP, DHP, DHP, 256, nullptr };
        sgemm<1><<<dim3(2, M_ROWS / 128, 1), 256>>>(p);
    }

    // similarity -> E, symmetric upper-triangle tiles (mirror via register transpose)
    {
        SimP p = { qproj, proj, E, seq };
        sim_kernel<<<dim3(136, 1, BB), 256>>>(p);
    }

    // x1 raw partials = E @ g1 (B direct from g12), split-K(2), fused denom partials
    {
        AdjP p = { E, g12, x1p, denp, seq };
        adj_kernel<<<dim3(2, TT / 128, BB), 256>>>(p);
    }
    // x2 = leaky(disadj @ g2) via windowed exponential scan
    scan_kernel<<<dim3(BB, TT / SC), DGC>>>(g12, x2);

    // frame_prob: combine split-K partials, /denom, leaky, classifier dot
    frame_kernel<<<M_ROWS / 8, 256>>>(x1p, x2, denp, seq, cls_w, cls_b, frame, out);
    clas_kernel<<<BB, 1024>>>(frame, seq, out);
}